// round 15
// baseline (speedup 1.0000x reference)
#include <cuda_runtime.h>
#include <cstdint>
#include <math.h>

// ----------------------------------------------------------------------------
// DenseCRF mean-field, permutohedral lattice. Round 15 = R10/R14 build phase +
// PERSISTENT mega-iteration kernel: splat(B+S) -> blur pair x3 (+spatial) ->
// slice+softmax as grid-stride phases with software grid barriers, one launch
// per mean-field iteration (8 launches+2 events -> 1 launch). Phase bodies are
// the proven R10 kernels verbatim.
// ----------------------------------------------------------------------------

#define HH 320
#define WW 320
#define NPIX (HH*WW)                 // 102400
#define NC 21
#define NCP 24
#define NQ4 6
#define SEGW 3
#define DBIL 5
#define DSP 2
#define MBIL (NPIX*(DBIL+1))         // 614400
#define MSP  (NPIX*(DSP+1))          // 307200
#define HBSZ (1u<<20)
#define HSSZ (1u<<17)
#define EMPTYK 0xFFFFFFFFFFFFFFFFULL

struct Globals {
    unsigned long long hkeyB[HBSZ];
    int                hidxB[HBSZ];
    int                hminB[HBSZ];
    unsigned long long hkeyS[HSSZ];
    int                hidxS[HSSZ];
    int                hminS[HSSZ];
    int countB, countS, pad_[2];
    unsigned long long ukeyB[MBIL];
    unsigned long long ukeyS[MSP];
    int   osB[NPIX*(DBIL+1)];
    float wsB[NPIX*(DBIL+1)];
    int   osS[NPIX*(DSP+1)];
    float wsS[NPIX*(DSP+1)];
    int2 nnB[(DBIL+1)*MBIL];
    int2 nnS[(DSP+1)*MSP];
    int pixCntB[NPIX], pixStartB[NPIX], pixFillB[NPIX], pixBsumB[512];
    int pixCntS[NPIX], pixStartS[NPIX], pixFillS[NPIX], pixBsumS[512];
    int   cntB[MBIL], startB[MBIL], fillB[MBIL];
    int   cntS[MSP],  startS[MSP],  fillS[MSP];
    int   bsumB[4096], bsumS[4096];
    int2  entB[NPIX*(DBIL+1)];
    int2  entS[NPIX*(DSP+1)];
    float4 bufB0[2ll*MBIL*SEGW];
    float4 bufB1[2ll*MBIL*SEGW];
    float4 bufS0[(long long)MSP*NQ4];
    float4 bufS1[(long long)MSP*NQ4];
    float nbuf0[MBIL];
    float nbuf1[MBIL];
    float nbufS0[MSP];
    float nbufS1[MSP];
    float normB[NPIX];
    float normS[NPIX];
    float4 Q[NPIX*NQ4];
};
__device__ Globals G;

// grid-barrier state (zero-init; returns to 0 after each mega launch: 4 barriers)
__device__ unsigned int gBarCount;
__device__ unsigned int gBarSense;

// ---------------- selectors --------------------------------------------------
template<int D> __device__ __forceinline__ unsigned long long* HK()   { return (D==DBIL)? G.hkeyB : G.hkeyS; }
template<int D> __device__ __forceinline__ int*                HI()   { return (D==DBIL)? G.hidxB : G.hidxS; }
template<int D> __device__ __forceinline__ int*                HMIN() { return (D==DBIL)? G.hminB : G.hminS; }
template<int D> __device__ __forceinline__ int*                CNTp() { return (D==DBIL)? &G.countB : &G.countS; }
template<int D> __device__ __forceinline__ unsigned long long* UK()   { return (D==DBIL)? G.ukeyB : G.ukeyS; }
template<int D> __device__ __forceinline__ int*                OS()   { return (D==DBIL)? G.osB : G.osS; }
template<int D> __device__ __forceinline__ float*              WSp()  { return (D==DBIL)? G.wsB : G.wsS; }
template<int D> __device__ __forceinline__ int2*               NN()   { return (D==DBIL)? G.nnB : G.nnS; }
template<int D> __device__ __forceinline__ int*                RCNT() { return (D==DBIL)? G.cntB : G.cntS; }
template<int D> __device__ __forceinline__ int*                RST()  { return (D==DBIL)? G.startB : G.startS; }
template<int D> __device__ __forceinline__ int*                RFIL() { return (D==DBIL)? G.fillB : G.fillS; }
template<int D> __device__ __forceinline__ int2*               ENT()  { return (D==DBIL)? G.entB : G.entS; }
template<int D> __device__ __forceinline__ int*                PCNT() { return (D==DBIL)? G.pixCntB : G.pixCntS; }
template<int D> __device__ __forceinline__ int*                PFIL() { return (D==DBIL)? G.pixFillB : G.pixFillS; }
template<int D> __device__ __forceinline__ float*              NB0()  { return (D==DBIL)? G.nbuf0 : G.nbufS0; }
template<int D> __device__ __forceinline__ float*              NB1()  { return (D==DBIL)? G.nbuf1 : G.nbufS1; }
template<int D> __host__ __device__ constexpr unsigned int HMSK(){ return (D==DBIL)? (HBSZ-1u) : (HSSZ-1u); }
template<int D> __host__ __device__ constexpr unsigned int HSZ (){ return (D==DBIL)? HBSZ : HSSZ; }
template<int D> __host__ __device__ constexpr int          MMAX(){ return (D==DBIL)? MBIL : MSP; }

// ---------------- hash -------------------------------------------------------
__device__ __forceinline__ unsigned int hmix(unsigned long long x, unsigned int mask){
    x ^= x >> 33; x *= 0xff51afd7ed558ccdULL;
    x ^= x >> 33; x *= 0xc4ceb9fe1a85ec53ULL;
    x ^= x >> 33;
    return (unsigned int)x & mask;
}
__device__ __forceinline__ unsigned int hinsert(unsigned long long* hk, unsigned int mask,
                                                unsigned long long key){
    unsigned int s = hmix(key, mask);
    while (true){
        unsigned long long prev = atomicCAS(&hk[s], EMPTYK, key);
        if (prev == EMPTYK || prev == key) return s;
        s = (s+1) & mask;
    }
}
__device__ __forceinline__ int hlookup(const unsigned long long* hk, const int* hi,
                                       unsigned int mask, unsigned long long key){
    unsigned int s = hmix(key, mask);
    while (true){
        unsigned long long k = hk[s];
        if (k == key)    return hi[s];
        if (k == EMPTYK) return -1;
        s = (s+1) & mask;
    }
}

// ---------------- lattice build ----------------------------------------------
template<int D>
__global__ void initHashK(){
    unsigned int s = blockIdx.x*blockDim.x + threadIdx.x;
    if (s < HSZ<D>()){ HK<D>()[s] = EMPTYK; HMIN<D>()[s] = 0x7FFFFFFF; }
    if (s == 0) *CNTp<D>() = 0;
}

template<int D>
__global__ void buildK(const float* __restrict__ image){
    int i = blockIdx.x*blockDim.x + threadIdx.x;
    if (i >= NPIX) return;
    float f[D];
    float x = (float)(i % WW), y = (float)(i / WW);
    if constexpr (D == DBIL){
        f[0] = x / 80.0f;  f[1] = y / 80.0f;
        f[2] = image[i*3+0] / 13.0f;
        f[3] = image[i*3+1] / 13.0f;
        f[4] = image[i*3+2] / 13.0f;
    } else {
        f[0] = x / 3.0f;   f[1] = y / 3.0f;
    }
    float cf[D];
    #pragma unroll
    for (int k=0;k<D;k++){
        double sc = sqrt(2.0/3.0) * (double)(D+1) / sqrt((double)((k+1)*(k+2)));
        cf[k] = f[k] * (float)sc;
    }
    float suf[D];
    { float s=0.f; for (int k=D-1;k>=0;k--){ s += cf[k]; suf[k]=s; } }
    float el[D+1];
    el[0] = suf[0];
    #pragma unroll
    for (int k=1;k<=D;k++){
        float t = (k<D) ? suf[k] : 0.0f;
        el[k] = t - (float)k * cf[k-1];
    }
    const float down = 1.0f/(float)(D+1);
    float rem0[D+1]; int rank[D+1]; int ssum=0;
    #pragma unroll
    for (int k=0;k<=D;k++){
        float rd = rintf(el[k]*down);
        rem0[k] = rd * (float)(D+1);
        ssum += (int)rd;
    }
    float diff[D+1];
    #pragma unroll
    for (int k=0;k<=D;k++) diff[k] = el[k] - rem0[k];
    #pragma unroll
    for (int a=0;a<=D;a++){
        int r = 0;
        #pragma unroll
        for (int b=0;b<=D;b++)
            if (diff[b] > diff[a] || (diff[b] == diff[a] && b < a)) r++;
        rank[a] = r + ssum;
    }
    #pragma unroll
    for (int k=0;k<=D;k++){
        if (rank[k] < 0)      { rank[k] += D+1; rem0[k] += (float)(D+1); }
        else if (rank[k] > D) { rank[k] -= D+1; rem0[k] -= (float)(D+1); }
    }
    float bb[D+2];
    #pragma unroll
    for (int k=0;k<D+2;k++) bb[k]=0.f;
    #pragma unroll
    for (int k=0;k<=D;k++){
        float v = (el[k]-rem0[k]) * down;
        bb[D   - rank[k]] += v;
        bb[D+1 - rank[k]] -= v;
    }
    bb[0] += 1.0f + bb[D+1];
    int key0[D];
    #pragma unroll
    for (int k=0;k<D;k++) key0[k] = (int)lrintf(rem0[k]);
    unsigned long long* hk = HK<D>();
    int* hmn = HMIN<D>();
    const unsigned int mask = HMSK<D>();
    #pragma unroll
    for (int r=0;r<=D;r++){
        unsigned long long pk = 0;
        #pragma unroll
        for (int k=0;k<D;k++){
            int canon = (rank[k] < D+1-r) ? r : r-(D+1);
            pk |= ((unsigned long long)(unsigned int)(key0[k]+canon+2048) & 0xFFFULL) << (12*k);
        }
        WSp<D>()[i*(D+1)+r] = bb[r];
        unsigned int slot = hinsert(hk, mask, pk);
        OS<D>()[i*(D+1)+r] = (int)slot;
        atomicMin(&hmn[slot], i);
    }
}

// ---- generic scan helpers ---------------------------------------------------
__global__ void gZero(int* a, int n){
    int t = blockIdx.x*blockDim.x + threadIdx.x;
    if (t < n) a[t] = 0;
}
__global__ void gScanA(const int* __restrict__ cnt, int* __restrict__ st,
                       int* __restrict__ bsum, int n){
    __shared__ int sh[256];
    int t = threadIdx.x;
    int g = blockIdx.x*256 + t;
    int v = (g < n) ? cnt[g] : 0;
    sh[t] = v; __syncthreads();
    #pragma unroll
    for (int o=1;o<256;o<<=1){
        int x = (t>=o) ? sh[t-o] : 0;
        __syncthreads();
        sh[t] += x;
        __syncthreads();
    }
    if (g < n) st[g] = sh[t] - v;
    if (t == 255) bsum[blockIdx.x] = sh[255];
}
__global__ void gScanB(int* __restrict__ bsum, int nb, int* total){
    __shared__ int sh[1024];
    int t = threadIdx.x;
    int carry = 0;
    for (int base=0; base<nb; base+=1024){
        int v = (base+t < nb) ? bsum[base+t] : 0;
        sh[t] = v; __syncthreads();
        for (int o=1;o<1024;o<<=1){
            int x = (t>=o) ? sh[t-o] : 0;
            __syncthreads();
            sh[t] += x;
            __syncthreads();
        }
        int tot = sh[1023];
        if (base+t < nb) bsum[base+t] = sh[t] - v + carry;
        __syncthreads();
        carry += tot;
    }
    if (t == 0 && total) *total = carry;
}
__global__ void gScanC(int* __restrict__ st, int* __restrict__ fill,
                       const int* __restrict__ bsum, int n){
    int g = blockIdx.x*256 + threadIdx.x;
    if (g >= n) return;
    int s = st[g] + bsum[g >> 8];
    st[g] = s;
    if (fill) fill[g] = s;
}

template<int D>
__global__ void countMinK(){
    unsigned int s = blockIdx.x*blockDim.x + threadIdx.x;
    if (s >= HSZ<D>()) return;
    if (HK<D>()[s] != EMPTYK)
        atomicAdd(&PCNT<D>()[HMIN<D>()[s]], 1);
}
template<int D>
__global__ void assignOrdK(){
    unsigned int s = blockIdx.x*blockDim.x + threadIdx.x;
    if (s >= HSZ<D>()) return;
    unsigned long long k = HK<D>()[s];
    if (k == EMPTYK) return;
    int idx = atomicAdd(&PFIL<D>()[HMIN<D>()[s]], 1);
    HI<D>()[s] = idx;
    UK<D>()[idx] = k;
}

template<int D>
__global__ void osRemapK(){
    int t = blockIdx.x*blockDim.x + threadIdx.x;
    if (t >= NPIX*(D+1)) return;
    OS<D>()[t] = HI<D>()[OS<D>()[t]];
}

template<int D>
__global__ void initNN2K(){
    long long t = (long long)blockIdx.x*blockDim.x + threadIdx.x;
    if (t < (long long)(D+1)*MMAX<D>())
        NN<D>()[t] = make_int2(-1, -1);
}

template<int D>
__global__ void neighK(){
    int m = blockIdx.x*blockDim.x + threadIdx.x;
    if (m >= *CNTp<D>()) return;
    unsigned long long k = UK<D>()[m];
    int c[D];
    #pragma unroll
    for (int t=0;t<D;t++) c[t] = (int)((k >> (12*t)) & 0xFFF) - 2048;
    unsigned long long* hk = HK<D>(); int* hi = HI<D>();
    const unsigned int mask = HMSK<D>();
    int* nnraw = (int*)NN<D>();
    #pragma unroll
    for (int j=0;j<=D;j++){
        unsigned long long p1=0;
        #pragma unroll
        for (int t=0;t<D;t++){
            int a1 = c[t]-1 + ((t==j)?(D+1):0);
            p1 |= ((unsigned long long)(unsigned int)(a1+2048) & 0xFFFULL) << (12*t);
        }
        int i1 = hlookup(hk, hi, mask, p1);
        long long slot = (long long)j*MMAX<D>() + m;
        nnraw[2*slot] = i1;
        if (i1 >= 0)
            nnraw[2*((long long)j*MMAX<D>() + i1) + 1] = m;
    }
}

// ---------------- CSR build --------------------------------------------------
template<int D>
__global__ void countRowsK(){
    int t = blockIdx.x*blockDim.x + threadIdx.x;
    if (t >= NPIX*(D+1)) return;
    atomicAdd(&RCNT<D>()[OS<D>()[t]], 1);
}
template<int D>
__global__ void fillK(){
    int t = blockIdx.x*blockDim.x + threadIdx.x;
    if (t >= NPIX*(D+1)) return;
    int m = OS<D>()[t];
    int p = atomicAdd(&RFIL<D>()[m], 1);
    ENT<D>()[p] = make_int2(t / (D+1), __float_as_int(WSp<D>()[t]));
}

// ---------------- norm filter ------------------------------------------------
template<int D>
__global__ void splatNCsrK(){
    for (int m = blockIdx.x*blockDim.x + threadIdx.x; m < *CNTp<D>();
         m += gridDim.x*blockDim.x){
        int s = RST<D>()[m], e = s + RCNT<D>()[m];
        float acc = 0.f;
        for (int k=s;k<e;k++) acc += __int_as_float(ENT<D>()[k].y);
        NB0<D>()[m] = acc;
    }
}
template<int D>
__global__ void blurN2K(int j1, int j2, int p){
    int M = *CNTp<D>();
    const float* in = p ? NB1<D>() : NB0<D>();
    float*      out = p ? NB0<D>() : NB1<D>();
    const int2* na = NN<D>() + (size_t)j1*MMAX<D>();
    const int2* nb = NN<D>() + (size_t)j2*MMAX<D>();
    for (int m = blockIdx.x*blockDim.x + threadIdx.x; m < M;
         m += gridDim.x*blockDim.x){
        int2 A = na[m]; int2 B = nb[m];
        float r = in[m];
        {
            float acc = 0.f;
            if (A.x >= 0) acc += in[A.x];
            if (A.y >= 0) acc += in[A.y];
            r += 0.5f*acc;
        }
        float accB = 0.f;
        if (B.x >= 0){
            float t = in[B.x];
            int2 c = na[B.x];
            float cc = 0.f;
            if (c.x >= 0) cc += in[c.x];
            if (c.y >= 0) cc += in[c.y];
            accB += t + 0.5f*cc;
        }
        if (B.y >= 0){
            float t = in[B.y];
            int2 c = na[B.y];
            float cc = 0.f;
            if (c.x >= 0) cc += in[c.x];
            if (c.y >= 0) cc += in[c.y];
            accB += t + 0.5f*cc;
        }
        out[m] = r + 0.5f*accB;
    }
}
template<int D>
__global__ void blurNK(int j, int p){
    int M = *CNTp<D>();
    const float* in = p ? NB1<D>() : NB0<D>();
    float*      out = p ? NB0<D>() : NB1<D>();
    for (int m = blockIdx.x*blockDim.x + threadIdx.x; m < M;
         m += gridDim.x*blockDim.x){
        int2 a = NN<D>()[j*MMAX<D>()+m];
        float va = (a.x >= 0) ? in[a.x] : 0.f;
        float vb = (a.y >= 0) ? in[a.y] : 0.f;
        out[m] = in[m] + 0.5f*(va + vb);
    }
}
template<int D>
__global__ void sliceNormK(float alpha, int p){
    int i = blockIdx.x*blockDim.x + threadIdx.x;
    if (i >= NPIX) return;
    const float* nb = p ? NB1<D>() : NB0<D>();
    const int*   os = OS<D>(); const float* ws = WSp<D>();
    float s = 0.f;
    #pragma unroll
    for (int j=0;j<=D;j++) s += ws[i*(D+1)+j] * nb[os[i*(D+1)+j]];
    float* nrm = (D==DBIL) ? G.normB : G.normS;
    nrm[i] = alpha * s + 1e-20f;
}

// ---------------- hot-loop device functions ----------------------------------
__device__ __forceinline__ float4 f4fma(float4 a, float s, float4 b){
    return make_float4(fmaf(a.x,s,b.x), fmaf(a.y,s,b.y), fmaf(a.z,s,b.z), fmaf(a.w,s,b.w));
}
__device__ __forceinline__ float4 f4add(float4 a, float4 b){
    return make_float4(a.x+b.x, a.y+b.y, a.z+b.z, a.w+b.w);
}

__device__ __forceinline__ void splatRowB(int m){
    int s = G.startB[m], e = s + G.cntB[m];
    float4 a0=make_float4(0,0,0,0), a1=a0, a2=a0, a3=a0, a4=a0, a5=a0;
    for (int k=s;k<e;k++){
        int2 ent = G.entB[k];
        float w = __int_as_float(ent.y);
        const float4* q = &G.Q[ent.x*NQ4];
        a0 = f4fma(q[0], w, a0);
        a1 = f4fma(q[1], w, a1);
        a2 = f4fma(q[2], w, a2);
        a3 = f4fma(q[3], w, a3);
        a4 = f4fma(q[4], w, a4);
        a5 = f4fma(q[5], w, a5);
    }
    float4* s0 = &G.bufB0[(size_t)m*SEGW];
    s0[0]=a0; s0[1]=a1; s0[2]=a2;
    float4* s1 = &G.bufB0[(size_t)MBIL*SEGW + (size_t)m*SEGW];
    s1[0]=a3; s1[1]=a4; s1[2]=a5;
}
__device__ __forceinline__ void splatRowS(int m){
    int s = G.startS[m], e = s + G.cntS[m];
    float4 a[NQ4];
    #pragma unroll
    for (int q=0;q<NQ4;q++) a[q]=make_float4(0,0,0,0);
    for (int k=s;k<e;k++){
        int2 ent = G.entS[k];
        float w = __int_as_float(ent.y);
        const float4* q = &G.Q[ent.x*NQ4];
        #pragma unroll
        for (int qi=0;qi<NQ4;qi++) a[qi] = f4fma(q[qi], w, a[qi]);
    }
    float4* o = &G.bufS0[(size_t)m*NQ4];
    #pragma unroll
    for (int qi=0;qi<NQ4;qi++) o[qi]=a[qi];
}

// quarter-thread pair-fused bilateral blur element (tid over 2*M*SEGW)
__device__ __forceinline__ void blur2Belem(long long tid, int M, int j1, int j2, int p){
    long long perseg = (long long)M*SEGW;
    int seg = (tid >= perseg) ? 1 : 0;
    long long rem = tid - (long long)seg*perseg;
    int m = (int)(rem / SEGW), q = (int)(rem % SEGW);
    size_t base = (size_t)seg*MBIL*SEGW;
    const float4* __restrict__ in  = (p ? G.bufB1 : G.bufB0) + base;
    float4*       __restrict__ out = (p ? G.bufB0 : G.bufB1) + base;
    const int2* __restrict__ na = G.nnB + (size_t)j1*MBIL;
    const int2* __restrict__ nb = G.nnB + (size_t)j2*MBIL;

    int2 A = na[m];
    int2 B = nb[m];

    float4 r = in[(size_t)m*SEGW+q];
    {
        float4 acc = make_float4(0,0,0,0);
        if (A.x >= 0) acc = in[(size_t)A.x*SEGW+q];
        if (A.y >= 0) acc = f4add(acc, in[(size_t)A.y*SEGW+q]);
        r = f4fma(acc, 0.5f, r);
    }
    float4 accB = make_float4(0,0,0,0);
    if (B.x >= 0){
        float4 t = in[(size_t)B.x*SEGW+q];
        int2 c = na[B.x];
        float4 cc = make_float4(0,0,0,0);
        if (c.x >= 0) cc = in[(size_t)c.x*SEGW+q];
        if (c.y >= 0) cc = f4add(cc, in[(size_t)c.y*SEGW+q]);
        accB = f4fma(cc, 0.5f, t);
    }
    if (B.y >= 0){
        float4 t = in[(size_t)B.y*SEGW+q];
        int2 c = na[B.y];
        float4 cc = make_float4(0,0,0,0);
        if (c.x >= 0) cc = in[(size_t)c.x*SEGW+q];
        if (c.y >= 0) cc = f4add(cc, in[(size_t)c.y*SEGW+q]);
        accB = f4add(accB, f4fma(cc, 0.5f, t));
    }
    out[(size_t)m*SEGW+q] = f4fma(accB, 0.5f, r);
}

__device__ __forceinline__ void blur2Selem(long long tid, int j1, int j2, int p){
    const float4* __restrict__ in  = p ? G.bufS1 : G.bufS0;
    float4*       __restrict__ out = p ? G.bufS0 : G.bufS1;
    const int2* __restrict__ na = G.nnS + (size_t)j1*MSP;
    const int2* __restrict__ nb = G.nnS + (size_t)j2*MSP;
    int m = (int)(tid / NQ4), q = (int)(tid % NQ4);
    int2 A = na[m];
    int2 B = nb[m];
    float4 r = in[(size_t)m*NQ4+q];
    {
        float4 acc = make_float4(0,0,0,0);
        if (A.x >= 0) acc = in[(size_t)A.x*NQ4+q];
        if (A.y >= 0) acc = f4add(acc, in[(size_t)A.y*NQ4+q]);
        r = f4fma(acc, 0.5f, r);
    }
    float4 accB = make_float4(0,0,0,0);
    if (B.x >= 0){
        float4 t = in[(size_t)B.x*NQ4+q];
        int2 c = na[B.x];
        float4 cc = make_float4(0,0,0,0);
        if (c.x >= 0) cc = in[(size_t)c.x*NQ4+q];
        if (c.y >= 0) cc = f4add(cc, in[(size_t)c.y*NQ4+q]);
        accB = f4fma(cc, 0.5f, t);
    }
    if (B.y >= 0){
        float4 t = in[(size_t)B.y*NQ4+q];
        int2 c = na[B.y];
        float4 cc = make_float4(0,0,0,0);
        if (c.x >= 0) cc = in[(size_t)c.x*NQ4+q];
        if (c.y >= 0) cc = f4add(cc, in[(size_t)c.y*NQ4+q]);
        accB = f4add(accB, f4fma(cc, 0.5f, t));
    }
    out[(size_t)m*NQ4+q] = f4fma(accB, 0.5f, r);
}

__device__ __forceinline__ void blurSelem(long long tid, int j, int p){
    const float4* __restrict__ in  = p ? G.bufS1 : G.bufS0;
    float4*       __restrict__ out = p ? G.bufS0 : G.bufS1;
    int m = (int)(tid / NQ4), q = (int)(tid % NQ4);
    int2 a = G.nnS[j*MSP+m];
    float4 self = in[(size_t)m*NQ4+q];
    float4 acc = make_float4(0.f,0.f,0.f,0.f);
    if (a.x >= 0) acc = in[(size_t)a.x*NQ4+q];
    if (a.y >= 0) acc = f4add(acc, in[(size_t)a.y*NQ4+q]);
    out[(size_t)m*NQ4+q] = f4fma(acc, 0.5f, self);
}

__device__ __forceinline__ void slicePixel(int i, const float* __restrict__ U,
                                           float* __restrict__ out, int writeOut,
                                           float fBmul, float fSmul){
    int   osb[DBIL+1]; float wsb[DBIL+1];
    #pragma unroll
    for (int j=0;j<=DBIL;j++){
        osb[j] = G.osB[i*(DBIL+1)+j];
        wsb[j] = G.wsB[i*(DBIL+1)+j];
    }
    int   oss[DSP+1]; float wss[DSP+1];
    #pragma unroll
    for (int j=0;j<=DSP;j++){
        oss[j] = G.osS[i*(DSP+1)+j];
        wss[j] = G.wsS[i*(DSP+1)+j];
    }
    float fB = fBmul / G.normB[i];
    float fS = fSmul / G.normS[i];

    const float4* __restrict__ bB = G.bufB1;
    const float4* __restrict__ bS = G.bufS0;

    float lg[NCP];
    float mx = -3.4e38f;
    #pragma unroll
    for (int q=0;q<NQ4;q++){
        int seg = (q < SEGW) ? 0 : 1;
        int qq  = q - seg*SEGW;
        size_t base = (size_t)seg*MBIL*SEGW + qq;
        float4 sB = make_float4(0.f,0.f,0.f,0.f);
        #pragma unroll
        for (int j=0;j<=DBIL;j++)
            sB = f4fma(bB[base + (size_t)osb[j]*SEGW], wsb[j], sB);
        float4 sS = make_float4(0.f,0.f,0.f,0.f);
        #pragma unroll
        for (int j=0;j<=DSP;j++)
            sS = f4fma(bS[(size_t)oss[j]*NQ4+q], wss[j], sS);
        #pragma unroll
        for (int k=0;k<4;k++){
            int ch = q*4+k;
            float m4 = (k==0)?(fB*sB.x+fS*sS.x):(k==1)?(fB*sB.y+fS*sS.y)
                     : (k==2)?(fB*sB.z+fS*sS.z):(fB*sB.w+fS*sS.w);
            float l = (ch < NC) ? (-U[i*NC+ch] + m4) : -3.4e38f;
            lg[q*4+k] = l;
            mx = fmaxf(mx, l);
        }
    }
    float sum = 0.f;
    #pragma unroll
    for (int c=0;c<NCP;c++){
        float e = (lg[c] > -1e37f) ? expf(lg[c]-mx) : 0.f;
        lg[c] = e; sum += e;
    }
    float inv = 1.0f / sum;
    #pragma unroll
    for (int q=0;q<NQ4;q++){
        float4 qv = make_float4(lg[q*4+0]*inv, lg[q*4+1]*inv, lg[q*4+2]*inv, lg[q*4+3]*inv);
        G.Q[i*NQ4+q] = qv;
        if (writeOut){
            int base = q*4;
            float* o = out + (long long)i*NC;
            o[base+0] = qv.x;
            if (base+1 < NC) o[base+1] = qv.y;
            if (base+2 < NC) o[base+2] = qv.z;
            if (base+3 < NC) o[base+3] = qv.w;
        }
    }
}

// ---------------- grid barrier ----------------------------------------------
__device__ __forceinline__ void gridBar(unsigned int* localSense, int nblocks){
    __syncthreads();
    if (threadIdx.x == 0){
        unsigned int s = *localSense ^ 1u;
        *localSense = s;
        __threadfence();
        if (atomicAdd(&gBarCount, 1u) == (unsigned int)nblocks - 1u){
            gBarCount = 0;
            __threadfence();
            atomicExch(&gBarSense, s);
        } else {
            while (atomicAdd(&gBarSense, 0u) != s) { }
        }
    }
    __syncthreads();
}

// ---------------- persistent mega-iteration kernel ---------------------------
__global__ void __launch_bounds__(256)
megaIterK(const float* __restrict__ U, float* __restrict__ out, int writeOut,
          float fBmul, float fSmul, int nblocks){
    __shared__ unsigned int localSense;
    if (threadIdx.x == 0) localSense = 0;
    __syncthreads();

    const int MB = G.countB, MS = G.countS;
    const long long stride = (long long)nblocks * blockDim.x;
    const long long t0 = (long long)blockIdx.x*blockDim.x + threadIdx.x;

    // Phase 0: splat both lattices
    for (long long t = t0; t < (long long)MB + MS; t += stride){
        if (t < MB) splatRowB((int)t);
        else        splatRowS((int)(t - MB));
    }
    gridBar(&localSense, nblocks);

    const long long nB = 2ll*MB*SEGW;
    const long long nS = (long long)MS*NQ4;

    // Phase 1: blur pair (0,1) B0->B1 ; spatial pair (0,1) S0->S1
    for (long long t = t0; t < nB + nS; t += stride){
        if (t < nB) blur2Belem(t, MB, 0, 1, 0);
        else        blur2Selem(t - nB, 0, 1, 0);
    }
    gridBar(&localSense, nblocks);

    // Phase 2: blur pair (2,3) B1->B0 ; spatial single (2) S1->S0
    for (long long t = t0; t < nB + nS; t += stride){
        if (t < nB) blur2Belem(t, MB, 2, 3, 1);
        else        blurSelem(t - nB, 2, 1);
    }
    gridBar(&localSense, nblocks);

    // Phase 3: blur pair (4,5) B0->B1
    for (long long t = t0; t < nB; t += stride){
        blur2Belem(t, MB, 4, 5, 0);
    }
    gridBar(&localSense, nblocks);

    // Phase 4: slice + softmax
    for (long long t = t0; t < NPIX; t += stride){
        slicePixel((int)t, U, out, writeOut, fBmul, fSmul);
    }
}

__global__ void softmax0K(const float* __restrict__ U){
    int i = blockIdx.x*blockDim.x + threadIdx.x;
    if (i >= NPIX) return;
    float t[NC];
    float mx = -3.4e38f;
    #pragma unroll
    for (int c=0;c<NC;c++){
        float l = -U[i*NC+c];
        t[c] = l; mx = fmaxf(mx, l);
    }
    float sum = 0.f;
    #pragma unroll
    for (int c=0;c<NC;c++){ float e = expf(t[c]-mx); t[c]=e; sum += e; }
    float inv = 1.0f / sum;
    float* q = (float*)&G.Q[i*NQ4];
    #pragma unroll
    for (int c=0;c<NC;c++) q[c] = t[c]*inv;
    #pragma unroll
    for (int c=NC;c<NCP;c++) q[c] = 0.f;
}

// ---------------- host -------------------------------------------------------
static inline unsigned int gridFor(long long n, int B){ return (unsigned int)((n + B - 1) / B); }

extern "C" void kernel_launch(void* const* d_in, const int* in_sizes, int n_in,
                              void* d_out, int out_size){
    const float* unary = nullptr;
    const float* image = nullptr;
    for (int k=0;k<n_in;k++){
        if      (in_sizes[k] == NPIX*NC) unary = (const float*)d_in[k];
        else if (in_sizes[k] == NPIX*3)  image = (const float*)d_in[k];
    }
    if (!unary || !image) return;
    float* out = (float*)d_out;
    const int B = 256;
    const int SG = 512;

    const float ALPHA_B = 32.0f/33.0f;
    const float ALPHA_S = 0.8f;
    const float WB = 10.0f, WSPA = 3.0f;

    static Globals* gptr = nullptr;
    static cudaStream_t sS = nullptr, s2 = nullptr;
    static cudaEvent_t eF=nullptr, eQ0=nullptr, eAsg=nullptr, eNeigh=nullptr,
                       eNSpl=nullptr, eNormB=nullptr, eSp=nullptr;
    static int megaBlocks = 0;
    if (!gptr){
        cudaGetSymbolAddress((void**)&gptr, G);
        cudaStreamCreateWithFlags(&sS, cudaStreamNonBlocking);
        cudaStreamCreateWithFlags(&s2, cudaStreamNonBlocking);
        cudaEventCreateWithFlags(&eF,    cudaEventDisableTiming);
        cudaEventCreateWithFlags(&eQ0,   cudaEventDisableTiming);
        cudaEventCreateWithFlags(&eAsg,  cudaEventDisableTiming);
        cudaEventCreateWithFlags(&eNeigh,cudaEventDisableTiming);
        cudaEventCreateWithFlags(&eNSpl, cudaEventDisableTiming);
        cudaEventCreateWithFlags(&eNormB,cudaEventDisableTiming);
        cudaEventCreateWithFlags(&eSp,   cudaEventDisableTiming);
        int dev = 0, sms = 0, occ = 0;
        cudaGetDevice(&dev);
        cudaDeviceGetAttribute(&sms, cudaDevAttrMultiProcessorCount, dev);
        cudaOccupancyMaxActiveBlocksPerMultiprocessor(&occ, megaIterK, B, 0);
        if (occ < 1) occ = 1;
        megaBlocks = sms * occ;
    }
    cudaStream_t s0 = 0;

    // ======== FORK ========
    cudaEventRecord(eF, s0);
    cudaStreamWaitEvent(sS, eF, 0);
    cudaStreamWaitEvent(s2, eF, 0);

    // ---- sS: initial softmax, then full spatial build + norms ----
    softmax0K<<<gridFor(NPIX,B), B, 0, sS>>>(unary);
    cudaEventRecord(eQ0, sS);

    initHashK<DSP><<<gridFor(HSSZ,B), B, 0, sS>>>();
    buildK<DSP><<<gridFor(NPIX,B), B, 0, sS>>>(image);
    gZero<<<gridFor(NPIX,B), B, 0, sS>>>(gptr->pixCntS, NPIX);
    countMinK<DSP><<<gridFor(HSSZ,B), B, 0, sS>>>();
    gScanA<<<NPIX/256, 256, 0, sS>>>(gptr->pixCntS, gptr->pixStartS, gptr->pixBsumS, NPIX);
    gScanB<<<1, 1024, 0, sS>>>(gptr->pixBsumS, NPIX/256, &gptr->countS);
    gScanC<<<NPIX/256, 256, 0, sS>>>(gptr->pixStartS, gptr->pixFillS, gptr->pixBsumS, NPIX);
    assignOrdK<DSP><<<gridFor(HSSZ,B), B, 0, sS>>>();
    osRemapK<DSP><<<gridFor(NPIX*(DSP+1),B), B, 0, sS>>>();
    initNN2K<DSP><<<gridFor((long long)(DSP+1)*MSP,B), B, 0, sS>>>();
    neighK<DSP><<<gridFor(MSP,B), B, 0, sS>>>();
    gZero<<<gridFor(MSP,B), B, 0, sS>>>(gptr->cntS, MSP);
    countRowsK<DSP><<<gridFor(NPIX*(DSP+1),B), B, 0, sS>>>();
    gScanA<<<MSP/256, 256, 0, sS>>>(gptr->cntS, gptr->startS, gptr->bsumS, MSP);
    gScanB<<<1, 1024, 0, sS>>>(gptr->bsumS, MSP/256, nullptr);
    gScanC<<<MSP/256, 256, 0, sS>>>(gptr->startS, gptr->fillS, gptr->bsumS, MSP);
    fillK<DSP><<<gridFor(NPIX*(DSP+1),B), B, 0, sS>>>();
    splatNCsrK<DSP><<<SG, B, 0, sS>>>();
    blurN2K<DSP><<<SG, B, 0, sS>>>(0, 1, 0);
    blurNK <DSP><<<SG, B, 0, sS>>>(2, 1);
    sliceNormK<DSP><<<gridFor(NPIX,B), B, 0, sS>>>(ALPHA_S, 0);
    cudaEventRecord(eSp, sS);

    // ---- s0: bilateral mainline;  s2: bilateral helper ----
    initHashK<DBIL><<<gridFor(HBSZ,B), B, 0, s0>>>();
    buildK<DBIL><<<gridFor(NPIX,B), B, 0, s0>>>(image);
    gZero<<<gridFor(NPIX,B), B, 0, s0>>>(gptr->pixCntB, NPIX);
    countMinK<DBIL><<<gridFor(HBSZ,B), B, 0, s0>>>();
    gScanA<<<NPIX/256, 256, 0, s0>>>(gptr->pixCntB, gptr->pixStartB, gptr->pixBsumB, NPIX);
    gScanB<<<1, 1024, 0, s0>>>(gptr->pixBsumB, NPIX/256, &gptr->countB);
    gScanC<<<NPIX/256, 256, 0, s0>>>(gptr->pixStartB, gptr->pixFillB, gptr->pixBsumB, NPIX);
    assignOrdK<DBIL><<<gridFor(HBSZ,B), B, 0, s0>>>();
    cudaEventRecord(eAsg, s0);

    cudaStreamWaitEvent(s2, eAsg, 0);
    initNN2K<DBIL><<<gridFor((long long)(DBIL+1)*MBIL,B), B, 0, s2>>>();
    neighK<DBIL><<<gridFor(MBIL,B), B, 0, s2>>>();
    cudaEventRecord(eNeigh, s2);

    osRemapK<DBIL><<<gridFor(NPIX*(DBIL+1),B), B, 0, s0>>>();
    gZero<<<gridFor(MBIL,B), B, 0, s0>>>(gptr->cntB, MBIL);
    countRowsK<DBIL><<<gridFor(NPIX*(DBIL+1),B), B, 0, s0>>>();
    gScanA<<<MBIL/256, 256, 0, s0>>>(gptr->cntB, gptr->startB, gptr->bsumB, MBIL);
    gScanB<<<1, 1024, 0, s0>>>(gptr->bsumB, MBIL/256, nullptr);
    gScanC<<<MBIL/256, 256, 0, s0>>>(gptr->startB, gptr->fillB, gptr->bsumB, MBIL);
    fillK<DBIL><<<gridFor(NPIX*(DBIL+1),B), B, 0, s0>>>();
    splatNCsrK<DBIL><<<gridFor(MBIL,B), B, 0, s0>>>();
    cudaEventRecord(eNSpl, s0);

    cudaStreamWaitEvent(s2, eNSpl, 0);
    blurN2K<DBIL><<<gridFor(MBIL,B), B, 0, s2>>>(0, 1, 0);
    blurN2K<DBIL><<<gridFor(MBIL,B), B, 0, s2>>>(2, 3, 1);
    blurN2K<DBIL><<<gridFor(MBIL,B), B, 0, s2>>>(4, 5, 0);
    sliceNormK<DBIL><<<gridFor(NPIX,B), B, 0, s2>>>(ALPHA_B, 1);
    cudaEventRecord(eNormB, s2);

    // ---- join EVERYTHING into s0 before the persistent iterations ----
    cudaStreamWaitEvent(s0, eQ0, 0);
    cudaStreamWaitEvent(s0, eSp, 0);
    cudaStreamWaitEvent(s0, eNeigh, 0);
    cudaStreamWaitEvent(s0, eNormB, 0);

    // ---- 5 mean-field iterations, one persistent launch each ----
    for (int it=0; it<5; ++it){
        megaIterK<<<megaBlocks, B, 0, s0>>>(
            unary, out, (it==4) ? 1 : 0,
            WB*ALPHA_B, WSPA*ALPHA_S, megaBlocks);
    }
}

// round 16
// speedup vs baseline: 1.0472x; 1.0472x over previous
#include <cuda_runtime.h>
#include <cstdint>
#include <math.h>

// ----------------------------------------------------------------------------
// DenseCRF mean-field, permutohedral lattice. Round 16 = champion (R10/R14)
// restored exactly, + one strictly-work-removing tweak: the final iteration's
// slice skips the dead G.Q write (Q is never read after the last slice).
// ----------------------------------------------------------------------------

#define HH 320
#define WW 320
#define NPIX (HH*WW)                 // 102400
#define NC 21
#define NCP 24
#define NQ4 6
#define SEGW 3
#define DBIL 5
#define DSP 2
#define MBIL (NPIX*(DBIL+1))         // 614400
#define MSP  (NPIX*(DSP+1))          // 307200
#define HBSZ (1u<<20)
#define HSSZ (1u<<17)
#define EMPTYK 0xFFFFFFFFFFFFFFFFULL

struct Globals {
    unsigned long long hkeyB[HBSZ];
    int                hidxB[HBSZ];
    int                hminB[HBSZ];
    unsigned long long hkeyS[HSSZ];
    int                hidxS[HSSZ];
    int                hminS[HSSZ];
    int countB, countS, pad_[2];
    unsigned long long ukeyB[MBIL];
    unsigned long long ukeyS[MSP];
    int   osB[NPIX*(DBIL+1)];
    float wsB[NPIX*(DBIL+1)];
    int   osS[NPIX*(DSP+1)];
    float wsS[NPIX*(DSP+1)];
    int2 nnB[(DBIL+1)*MBIL];
    int2 nnS[(DSP+1)*MSP];
    int pixCntB[NPIX], pixStartB[NPIX], pixFillB[NPIX], pixBsumB[512];
    int pixCntS[NPIX], pixStartS[NPIX], pixFillS[NPIX], pixBsumS[512];
    int   cntB[MBIL], startB[MBIL], fillB[MBIL];
    int   cntS[MSP],  startS[MSP],  fillS[MSP];
    int   bsumB[4096], bsumS[4096];
    int2  entB[NPIX*(DBIL+1)];
    int2  entS[NPIX*(DSP+1)];
    float4 bufB0[2ll*MBIL*SEGW];
    float4 bufB1[2ll*MBIL*SEGW];
    float4 bufS0[(long long)MSP*NQ4];
    float4 bufS1[(long long)MSP*NQ4];
    float nbuf0[MBIL];
    float nbuf1[MBIL];
    float nbufS0[MSP];
    float nbufS1[MSP];
    float normB[NPIX];
    float normS[NPIX];
    float4 Q[NPIX*NQ4];
};
__device__ Globals G;

// ---------------- selectors --------------------------------------------------
template<int D> __device__ __forceinline__ unsigned long long* HK()   { return (D==DBIL)? G.hkeyB : G.hkeyS; }
template<int D> __device__ __forceinline__ int*                HI()   { return (D==DBIL)? G.hidxB : G.hidxS; }
template<int D> __device__ __forceinline__ int*                HMIN() { return (D==DBIL)? G.hminB : G.hminS; }
template<int D> __device__ __forceinline__ int*                CNTp() { return (D==DBIL)? &G.countB : &G.countS; }
template<int D> __device__ __forceinline__ unsigned long long* UK()   { return (D==DBIL)? G.ukeyB : G.ukeyS; }
template<int D> __device__ __forceinline__ int*                OS()   { return (D==DBIL)? G.osB : G.osS; }
template<int D> __device__ __forceinline__ float*              WSp()  { return (D==DBIL)? G.wsB : G.wsS; }
template<int D> __device__ __forceinline__ int2*               NN()   { return (D==DBIL)? G.nnB : G.nnS; }
template<int D> __device__ __forceinline__ int*                RCNT() { return (D==DBIL)? G.cntB : G.cntS; }
template<int D> __device__ __forceinline__ int*                RST()  { return (D==DBIL)? G.startB : G.startS; }
template<int D> __device__ __forceinline__ int*                RFIL() { return (D==DBIL)? G.fillB : G.fillS; }
template<int D> __device__ __forceinline__ int2*               ENT()  { return (D==DBIL)? G.entB : G.entS; }
template<int D> __device__ __forceinline__ int*                PCNT() { return (D==DBIL)? G.pixCntB : G.pixCntS; }
template<int D> __device__ __forceinline__ int*                PFIL() { return (D==DBIL)? G.pixFillB : G.pixFillS; }
template<int D> __device__ __forceinline__ float*              NB0()  { return (D==DBIL)? G.nbuf0 : G.nbufS0; }
template<int D> __device__ __forceinline__ float*              NB1()  { return (D==DBIL)? G.nbuf1 : G.nbufS1; }
template<int D> __host__ __device__ constexpr unsigned int HMSK(){ return (D==DBIL)? (HBSZ-1u) : (HSSZ-1u); }
template<int D> __host__ __device__ constexpr unsigned int HSZ (){ return (D==DBIL)? HBSZ : HSSZ; }
template<int D> __host__ __device__ constexpr int          MMAX(){ return (D==DBIL)? MBIL : MSP; }

// ---------------- hash -------------------------------------------------------
__device__ __forceinline__ unsigned int hmix(unsigned long long x, unsigned int mask){
    x ^= x >> 33; x *= 0xff51afd7ed558ccdULL;
    x ^= x >> 33; x *= 0xc4ceb9fe1a85ec53ULL;
    x ^= x >> 33;
    return (unsigned int)x & mask;
}
__device__ __forceinline__ unsigned int hinsert(unsigned long long* hk, unsigned int mask,
                                                unsigned long long key){
    unsigned int s = hmix(key, mask);
    while (true){
        unsigned long long prev = atomicCAS(&hk[s], EMPTYK, key);
        if (prev == EMPTYK || prev == key) return s;
        s = (s+1) & mask;
    }
}
__device__ __forceinline__ int hlookup(const unsigned long long* hk, const int* hi,
                                       unsigned int mask, unsigned long long key){
    unsigned int s = hmix(key, mask);
    while (true){
        unsigned long long k = hk[s];
        if (k == key)    return hi[s];
        if (k == EMPTYK) return -1;
        s = (s+1) & mask;
    }
}

// ---------------- lattice build ----------------------------------------------
template<int D>
__global__ void initHashK(){
    unsigned int s = blockIdx.x*blockDim.x + threadIdx.x;
    if (s < HSZ<D>()){ HK<D>()[s] = EMPTYK; HMIN<D>()[s] = 0x7FFFFFFF; }
    if (s == 0) *CNTp<D>() = 0;
}

template<int D>
__global__ void buildK(const float* __restrict__ image){
    int i = blockIdx.x*blockDim.x + threadIdx.x;
    if (i >= NPIX) return;
    float f[D];
    float x = (float)(i % WW), y = (float)(i / WW);
    if constexpr (D == DBIL){
        f[0] = x / 80.0f;  f[1] = y / 80.0f;
        f[2] = image[i*3+0] / 13.0f;
        f[3] = image[i*3+1] / 13.0f;
        f[4] = image[i*3+2] / 13.0f;
    } else {
        f[0] = x / 3.0f;   f[1] = y / 3.0f;
    }
    float cf[D];
    #pragma unroll
    for (int k=0;k<D;k++){
        double sc = sqrt(2.0/3.0) * (double)(D+1) / sqrt((double)((k+1)*(k+2)));
        cf[k] = f[k] * (float)sc;
    }
    float suf[D];
    { float s=0.f; for (int k=D-1;k>=0;k--){ s += cf[k]; suf[k]=s; } }
    float el[D+1];
    el[0] = suf[0];
    #pragma unroll
    for (int k=1;k<=D;k++){
        float t = (k<D) ? suf[k] : 0.0f;
        el[k] = t - (float)k * cf[k-1];
    }
    const float down = 1.0f/(float)(D+1);
    float rem0[D+1]; int rank[D+1]; int ssum=0;
    #pragma unroll
    for (int k=0;k<=D;k++){
        float rd = rintf(el[k]*down);
        rem0[k] = rd * (float)(D+1);
        ssum += (int)rd;
    }
    float diff[D+1];
    #pragma unroll
    for (int k=0;k<=D;k++) diff[k] = el[k] - rem0[k];
    #pragma unroll
    for (int a=0;a<=D;a++){
        int r = 0;
        #pragma unroll
        for (int b=0;b<=D;b++)
            if (diff[b] > diff[a] || (diff[b] == diff[a] && b < a)) r++;
        rank[a] = r + ssum;
    }
    #pragma unroll
    for (int k=0;k<=D;k++){
        if (rank[k] < 0)      { rank[k] += D+1; rem0[k] += (float)(D+1); }
        else if (rank[k] > D) { rank[k] -= D+1; rem0[k] -= (float)(D+1); }
    }
    float bb[D+2];
    #pragma unroll
    for (int k=0;k<D+2;k++) bb[k]=0.f;
    #pragma unroll
    for (int k=0;k<=D;k++){
        float v = (el[k]-rem0[k]) * down;
        bb[D   - rank[k]] += v;
        bb[D+1 - rank[k]] -= v;
    }
    bb[0] += 1.0f + bb[D+1];
    int key0[D];
    #pragma unroll
    for (int k=0;k<D;k++) key0[k] = (int)lrintf(rem0[k]);
    unsigned long long* hk = HK<D>();
    int* hmn = HMIN<D>();
    const unsigned int mask = HMSK<D>();
    #pragma unroll
    for (int r=0;r<=D;r++){
        unsigned long long pk = 0;
        #pragma unroll
        for (int k=0;k<D;k++){
            int canon = (rank[k] < D+1-r) ? r : r-(D+1);
            pk |= ((unsigned long long)(unsigned int)(key0[k]+canon+2048) & 0xFFFULL) << (12*k);
        }
        WSp<D>()[i*(D+1)+r] = bb[r];
        unsigned int slot = hinsert(hk, mask, pk);
        OS<D>()[i*(D+1)+r] = (int)slot;
        atomicMin(&hmn[slot], i);
    }
}

// ---- generic scan helpers ---------------------------------------------------
__global__ void gZero(int* a, int n){
    int t = blockIdx.x*blockDim.x + threadIdx.x;
    if (t < n) a[t] = 0;
}
__global__ void gScanA(const int* __restrict__ cnt, int* __restrict__ st,
                       int* __restrict__ bsum, int n){
    __shared__ int sh[256];
    int t = threadIdx.x;
    int g = blockIdx.x*256 + t;
    int v = (g < n) ? cnt[g] : 0;
    sh[t] = v; __syncthreads();
    #pragma unroll
    for (int o=1;o<256;o<<=1){
        int x = (t>=o) ? sh[t-o] : 0;
        __syncthreads();
        sh[t] += x;
        __syncthreads();
    }
    if (g < n) st[g] = sh[t] - v;
    if (t == 255) bsum[blockIdx.x] = sh[255];
}
__global__ void gScanB(int* __restrict__ bsum, int nb, int* total){
    __shared__ int sh[1024];
    int t = threadIdx.x;
    int carry = 0;
    for (int base=0; base<nb; base+=1024){
        int v = (base+t < nb) ? bsum[base+t] : 0;
        sh[t] = v; __syncthreads();
        for (int o=1;o<1024;o<<=1){
            int x = (t>=o) ? sh[t-o] : 0;
            __syncthreads();
            sh[t] += x;
            __syncthreads();
        }
        int tot = sh[1023];
        if (base+t < nb) bsum[base+t] = sh[t] - v + carry;
        __syncthreads();
        carry += tot;
    }
    if (t == 0 && total) *total = carry;
}
__global__ void gScanC(int* __restrict__ st, int* __restrict__ fill,
                       const int* __restrict__ bsum, int n){
    int g = blockIdx.x*256 + threadIdx.x;
    if (g >= n) return;
    int s = st[g] + bsum[g >> 8];
    st[g] = s;
    if (fill) fill[g] = s;
}

template<int D>
__global__ void countMinK(){
    unsigned int s = blockIdx.x*blockDim.x + threadIdx.x;
    if (s >= HSZ<D>()) return;
    if (HK<D>()[s] != EMPTYK)
        atomicAdd(&PCNT<D>()[HMIN<D>()[s]], 1);
}
template<int D>
__global__ void assignOrdK(){
    unsigned int s = blockIdx.x*blockDim.x + threadIdx.x;
    if (s >= HSZ<D>()) return;
    unsigned long long k = HK<D>()[s];
    if (k == EMPTYK) return;
    int idx = atomicAdd(&PFIL<D>()[HMIN<D>()[s]], 1);
    HI<D>()[s] = idx;
    UK<D>()[idx] = k;
}

template<int D>
__global__ void osRemapK(){
    int t = blockIdx.x*blockDim.x + threadIdx.x;
    if (t >= NPIX*(D+1)) return;
    OS<D>()[t] = HI<D>()[OS<D>()[t]];
}

template<int D>
__global__ void initNN2K(){
    long long t = (long long)blockIdx.x*blockDim.x + threadIdx.x;
    if (t < (long long)(D+1)*MMAX<D>())
        NN<D>()[t] = make_int2(-1, -1);
}

template<int D>
__global__ void neighK(){
    int m = blockIdx.x*blockDim.x + threadIdx.x;
    if (m >= *CNTp<D>()) return;
    unsigned long long k = UK<D>()[m];
    int c[D];
    #pragma unroll
    for (int t=0;t<D;t++) c[t] = (int)((k >> (12*t)) & 0xFFF) - 2048;
    unsigned long long* hk = HK<D>(); int* hi = HI<D>();
    const unsigned int mask = HMSK<D>();
    int* nnraw = (int*)NN<D>();
    #pragma unroll
    for (int j=0;j<=D;j++){
        unsigned long long p1=0;
        #pragma unroll
        for (int t=0;t<D;t++){
            int a1 = c[t]-1 + ((t==j)?(D+1):0);
            p1 |= ((unsigned long long)(unsigned int)(a1+2048) & 0xFFFULL) << (12*t);
        }
        int i1 = hlookup(hk, hi, mask, p1);
        long long slot = (long long)j*MMAX<D>() + m;
        nnraw[2*slot] = i1;
        if (i1 >= 0)
            nnraw[2*((long long)j*MMAX<D>() + i1) + 1] = m;
    }
}

// ---------------- CSR build --------------------------------------------------
template<int D>
__global__ void countRowsK(){
    int t = blockIdx.x*blockDim.x + threadIdx.x;
    if (t >= NPIX*(D+1)) return;
    atomicAdd(&RCNT<D>()[OS<D>()[t]], 1);
}
template<int D>
__global__ void fillK(){
    int t = blockIdx.x*blockDim.x + threadIdx.x;
    if (t >= NPIX*(D+1)) return;
    int m = OS<D>()[t];
    int p = atomicAdd(&RFIL<D>()[m], 1);
    ENT<D>()[p] = make_int2(t / (D+1), __float_as_int(WSp<D>()[t]));
}

// ---------------- norm filter ------------------------------------------------
template<int D>
__global__ void splatNCsrK(){
    for (int m = blockIdx.x*blockDim.x + threadIdx.x; m < *CNTp<D>();
         m += gridDim.x*blockDim.x){
        int s = RST<D>()[m], e = s + RCNT<D>()[m];
        float acc = 0.f;
        for (int k=s;k<e;k++) acc += __int_as_float(ENT<D>()[k].y);
        NB0<D>()[m] = acc;
    }
}
template<int D>
__global__ void blurN2K(int j1, int j2, int p){
    int M = *CNTp<D>();
    const float* in = p ? NB1<D>() : NB0<D>();
    float*      out = p ? NB0<D>() : NB1<D>();
    const int2* na = NN<D>() + (size_t)j1*MMAX<D>();
    const int2* nb = NN<D>() + (size_t)j2*MMAX<D>();
    for (int m = blockIdx.x*blockDim.x + threadIdx.x; m < M;
         m += gridDim.x*blockDim.x){
        int2 A = na[m]; int2 B = nb[m];
        float r = in[m];
        {
            float acc = 0.f;
            if (A.x >= 0) acc += in[A.x];
            if (A.y >= 0) acc += in[A.y];
            r += 0.5f*acc;
        }
        float accB = 0.f;
        if (B.x >= 0){
            float t = in[B.x];
            int2 c = na[B.x];
            float cc = 0.f;
            if (c.x >= 0) cc += in[c.x];
            if (c.y >= 0) cc += in[c.y];
            accB += t + 0.5f*cc;
        }
        if (B.y >= 0){
            float t = in[B.y];
            int2 c = na[B.y];
            float cc = 0.f;
            if (c.x >= 0) cc += in[c.x];
            if (c.y >= 0) cc += in[c.y];
            accB += t + 0.5f*cc;
        }
        out[m] = r + 0.5f*accB;
    }
}
template<int D>
__global__ void blurNK(int j, int p){
    int M = *CNTp<D>();
    const float* in = p ? NB1<D>() : NB0<D>();
    float*      out = p ? NB0<D>() : NB1<D>();
    for (int m = blockIdx.x*blockDim.x + threadIdx.x; m < M;
         m += gridDim.x*blockDim.x){
        int2 a = NN<D>()[j*MMAX<D>()+m];
        float va = (a.x >= 0) ? in[a.x] : 0.f;
        float vb = (a.y >= 0) ? in[a.y] : 0.f;
        out[m] = in[m] + 0.5f*(va + vb);
    }
}
template<int D>
__global__ void sliceNormK(float alpha, int p){
    int i = blockIdx.x*blockDim.x + threadIdx.x;
    if (i >= NPIX) return;
    const float* nb = p ? NB1<D>() : NB0<D>();
    const int*   os = OS<D>(); const float* ws = WSp<D>();
    float s = 0.f;
    #pragma unroll
    for (int j=0;j<=D;j++) s += ws[i*(D+1)+j] * nb[os[i*(D+1)+j]];
    float* nrm = (D==DBIL) ? G.normB : G.normS;
    nrm[i] = alpha * s + 1e-20f;
}

// ---------------- hot-loop kernels -------------------------------------------
__device__ __forceinline__ float4 f4fma(float4 a, float s, float4 b){
    return make_float4(fmaf(a.x,s,b.x), fmaf(a.y,s,b.y), fmaf(a.z,s,b.z), fmaf(a.w,s,b.w));
}
__device__ __forceinline__ float4 f4add(float4 a, float4 b){
    return make_float4(a.x+b.x, a.y+b.y, a.z+b.z, a.w+b.w);
}

__global__ void splatCsrBK(){
    int m = blockIdx.x*blockDim.x + threadIdx.x;
    if (m >= G.countB) return;
    int s = G.startB[m], e = s + G.cntB[m];
    float4 a0=make_float4(0,0,0,0), a1=a0, a2=a0, a3=a0, a4=a0, a5=a0;
    for (int k=s;k<e;k++){
        int2 ent = G.entB[k];
        float w = __int_as_float(ent.y);
        const float4* q = &G.Q[ent.x*NQ4];
        a0 = f4fma(q[0], w, a0);
        a1 = f4fma(q[1], w, a1);
        a2 = f4fma(q[2], w, a2);
        a3 = f4fma(q[3], w, a3);
        a4 = f4fma(q[4], w, a4);
        a5 = f4fma(q[5], w, a5);
    }
    float4* s0 = &G.bufB0[(size_t)m*SEGW];
    s0[0]=a0; s0[1]=a1; s0[2]=a2;
    float4* s1 = &G.bufB0[(size_t)MBIL*SEGW + (size_t)m*SEGW];
    s1[0]=a3; s1[1]=a4; s1[2]=a5;
}
__global__ void splatCsrSK(){
    int M = G.countS;
    for (int m = blockIdx.x*blockDim.x + threadIdx.x; m < M;
         m += gridDim.x*blockDim.x){
        int s = G.startS[m], e = s + G.cntS[m];
        float4 a[NQ4];
        #pragma unroll
        for (int q=0;q<NQ4;q++) a[q]=make_float4(0,0,0,0);
        for (int k=s;k<e;k++){
            int2 ent = G.entS[k];
            float w = __int_as_float(ent.y);
            const float4* q = &G.Q[ent.x*NQ4];
            #pragma unroll
            for (int qi=0;qi<NQ4;qi++) a[qi] = f4fma(q[qi], w, a[qi]);
        }
        float4* o = &G.bufS0[(size_t)m*NQ4];
        #pragma unroll
        for (int qi=0;qi<NQ4;qi++) o[qi]=a[qi];
    }
}

__global__ void blur2BK(int j1, int j2, int p){
    long long tid = (long long)blockIdx.x*blockDim.x + threadIdx.x;
    int M = G.countB;
    long long perseg = (long long)M*SEGW;
    int seg = (tid >= perseg) ? 1 : 0;
    long long rem = tid - (long long)seg*perseg;
    int m = (int)(rem / SEGW), q = (int)(rem % SEGW);
    if (m >= M) return;
    size_t base = (size_t)seg*MBIL*SEGW;
    const float4* __restrict__ in  = (p ? G.bufB1 : G.bufB0) + base;
    float4*       __restrict__ out = (p ? G.bufB0 : G.bufB1) + base;
    const int2* __restrict__ na = G.nnB + (size_t)j1*MBIL;
    const int2* __restrict__ nb = G.nnB + (size_t)j2*MBIL;

    int2 A = na[m];
    int2 B = nb[m];

    float4 r = in[(size_t)m*SEGW+q];
    {
        float4 acc = make_float4(0,0,0,0);
        if (A.x >= 0) acc = in[(size_t)A.x*SEGW+q];
        if (A.y >= 0) acc = f4add(acc, in[(size_t)A.y*SEGW+q]);
        r = f4fma(acc, 0.5f, r);
    }
    float4 accB = make_float4(0,0,0,0);
    if (B.x >= 0){
        float4 t = in[(size_t)B.x*SEGW+q];
        int2 c = na[B.x];
        float4 cc = make_float4(0,0,0,0);
        if (c.x >= 0) cc = in[(size_t)c.x*SEGW+q];
        if (c.y >= 0) cc = f4add(cc, in[(size_t)c.y*SEGW+q]);
        accB = f4fma(cc, 0.5f, t);
    }
    if (B.y >= 0){
        float4 t = in[(size_t)B.y*SEGW+q];
        int2 c = na[B.y];
        float4 cc = make_float4(0,0,0,0);
        if (c.x >= 0) cc = in[(size_t)c.x*SEGW+q];
        if (c.y >= 0) cc = f4add(cc, in[(size_t)c.y*SEGW+q]);
        accB = f4add(accB, f4fma(cc, 0.5f, t));
    }
    out[(size_t)m*SEGW+q] = f4fma(accB, 0.5f, r);
}

__global__ void blur2SK(int j1, int j2, int p){
    int M = G.countS;
    const float4* __restrict__ in  = p ? G.bufS1 : G.bufS0;
    float4*       __restrict__ out = p ? G.bufS0 : G.bufS1;
    const int2* __restrict__ na = G.nnS + (size_t)j1*MSP;
    const int2* __restrict__ nb = G.nnS + (size_t)j2*MSP;
    long long total = (long long)M*NQ4;
    for (long long tid = (long long)blockIdx.x*blockDim.x + threadIdx.x;
         tid < total; tid += (long long)gridDim.x*blockDim.x){
        int m = (int)(tid / NQ4), q = (int)(tid % NQ4);
        int2 A = na[m];
        int2 B = nb[m];
        float4 r = in[(size_t)m*NQ4+q];
        {
            float4 acc = make_float4(0,0,0,0);
            if (A.x >= 0) acc = in[(size_t)A.x*NQ4+q];
            if (A.y >= 0) acc = f4add(acc, in[(size_t)A.y*NQ4+q]);
            r = f4fma(acc, 0.5f, r);
        }
        float4 accB = make_float4(0,0,0,0);
        if (B.x >= 0){
            float4 t = in[(size_t)B.x*NQ4+q];
            int2 c = na[B.x];
            float4 cc = make_float4(0,0,0,0);
            if (c.x >= 0) cc = in[(size_t)c.x*NQ4+q];
            if (c.y >= 0) cc = f4add(cc, in[(size_t)c.y*NQ4+q]);
            accB = f4fma(cc, 0.5f, t);
        }
        if (B.y >= 0){
            float4 t = in[(size_t)B.y*NQ4+q];
            int2 c = na[B.y];
            float4 cc = make_float4(0,0,0,0);
            if (c.x >= 0) cc = in[(size_t)c.x*NQ4+q];
            if (c.y >= 0) cc = f4add(cc, in[(size_t)c.y*NQ4+q]);
            accB = f4add(accB, f4fma(cc, 0.5f, t));
        }
        out[(size_t)m*NQ4+q] = f4fma(accB, 0.5f, r);
    }
}

__global__ void blurSK(int j, int p){
    int M = G.countS;
    const float4* __restrict__ in  = p ? G.bufS1 : G.bufS0;
    float4*       __restrict__ out = p ? G.bufS0 : G.bufS1;
    long long total = (long long)M*NQ4;
    for (long long tid = (long long)blockIdx.x*blockDim.x + threadIdx.x;
         tid < total; tid += (long long)gridDim.x*blockDim.x){
        int m = (int)(tid / NQ4), q = (int)(tid % NQ4);
        int2 a = G.nnS[j*MSP+m];
        float4 self = in[(size_t)m*NQ4+q];
        float4 acc = make_float4(0.f,0.f,0.f,0.f);
        if (a.x >= 0) acc = in[(size_t)a.x*NQ4+q];
        if (a.y >= 0) acc = f4add(acc, in[(size_t)a.y*NQ4+q]);
        out[(size_t)m*NQ4+q] = f4fma(acc, 0.5f, self);
    }
}

__global__ void sliceSoftmaxK(const float* __restrict__ U,
                              float* __restrict__ out, int writeOut,
                              float fBmul, float fSmul){
    int i = blockIdx.x*blockDim.x + threadIdx.x;
    if (i >= NPIX) return;

    int   osb[DBIL+1]; float wsb[DBIL+1];
    #pragma unroll
    for (int j=0;j<=DBIL;j++){
        osb[j] = G.osB[i*(DBIL+1)+j];
        wsb[j] = G.wsB[i*(DBIL+1)+j];
    }
    int   oss[DSP+1]; float wss[DSP+1];
    #pragma unroll
    for (int j=0;j<=DSP;j++){
        oss[j] = G.osS[i*(DSP+1)+j];
        wss[j] = G.wsS[i*(DSP+1)+j];
    }
    float fB = fBmul / G.normB[i];
    float fS = fSmul / G.normS[i];

    const float4* __restrict__ bB = G.bufB1;
    const float4* __restrict__ bS = G.bufS0;

    float lg[NCP];
    float mx = -3.4e38f;
    #pragma unroll
    for (int q=0;q<NQ4;q++){
        int seg = (q < SEGW) ? 0 : 1;
        int qq  = q - seg*SEGW;
        size_t base = (size_t)seg*MBIL*SEGW + qq;
        float4 sB = make_float4(0.f,0.f,0.f,0.f);
        #pragma unroll
        for (int j=0;j<=DBIL;j++)
            sB = f4fma(bB[base + (size_t)osb[j]*SEGW], wsb[j], sB);
        float4 sS = make_float4(0.f,0.f,0.f,0.f);
        #pragma unroll
        for (int j=0;j<=DSP;j++)
            sS = f4fma(bS[(size_t)oss[j]*NQ4+q], wss[j], sS);
        #pragma unroll
        for (int k=0;k<4;k++){
            int ch = q*4+k;
            float m4 = (k==0)?(fB*sB.x+fS*sS.x):(k==1)?(fB*sB.y+fS*sS.y)
                     : (k==2)?(fB*sB.z+fS*sS.z):(fB*sB.w+fS*sS.w);
            float l = (ch < NC) ? (-U[i*NC+ch] + m4) : -3.4e38f;
            lg[q*4+k] = l;
            mx = fmaxf(mx, l);
        }
    }
    float sum = 0.f;
    #pragma unroll
    for (int c=0;c<NCP;c++){
        float e = (lg[c] > -1e37f) ? expf(lg[c]-mx) : 0.f;
        lg[c] = e; sum += e;
    }
    float inv = 1.0f / sum;
    if (writeOut){
        // final iteration: Q is dead after this kernel — write only the output
        float* o = out + (long long)i*NC;
        #pragma unroll
        for (int c=0;c<NC;c++) o[c] = lg[c]*inv;
    } else {
        #pragma unroll
        for (int q=0;q<NQ4;q++){
            float4 qv = make_float4(lg[q*4+0]*inv, lg[q*4+1]*inv,
                                    lg[q*4+2]*inv, lg[q*4+3]*inv);
            G.Q[i*NQ4+q] = qv;
        }
    }
}

__global__ void softmax0K(const float* __restrict__ U){
    int i = blockIdx.x*blockDim.x + threadIdx.x;
    if (i >= NPIX) return;
    float t[NC];
    float mx = -3.4e38f;
    #pragma unroll
    for (int c=0;c<NC;c++){
        float l = -U[i*NC+c];
        t[c] = l; mx = fmaxf(mx, l);
    }
    float sum = 0.f;
    #pragma unroll
    for (int c=0;c<NC;c++){ float e = expf(t[c]-mx); t[c]=e; sum += e; }
    float inv = 1.0f / sum;
    float* q = (float*)&G.Q[i*NQ4];
    #pragma unroll
    for (int c=0;c<NC;c++) q[c] = t[c]*inv;
    #pragma unroll
    for (int c=NC;c<NCP;c++) q[c] = 0.f;
}

// ---------------- host -------------------------------------------------------
static inline unsigned int gridFor(long long n, int B){ return (unsigned int)((n + B - 1) / B); }

extern "C" void kernel_launch(void* const* d_in, const int* in_sizes, int n_in,
                              void* d_out, int out_size){
    const float* unary = nullptr;
    const float* image = nullptr;
    for (int k=0;k<n_in;k++){
        if      (in_sizes[k] == NPIX*NC) unary = (const float*)d_in[k];
        else if (in_sizes[k] == NPIX*3)  image = (const float*)d_in[k];
    }
    if (!unary || !image) return;
    float* out = (float*)d_out;
    const int B = 256;
    const int SG = 512;

    const float ALPHA_B = 32.0f/33.0f;
    const float ALPHA_S = 0.8f;
    const float WB = 10.0f, WSPA = 3.0f;

    static Globals* gptr = nullptr;
    static cudaStream_t sS = nullptr, s2 = nullptr;
    static cudaEvent_t eF=nullptr, eQ0=nullptr, eAsg=nullptr, eNeigh=nullptr,
                       eNSpl=nullptr, eNormB=nullptr, eSp=nullptr, eJoin=nullptr;
    if (!gptr){
        cudaGetSymbolAddress((void**)&gptr, G);
        cudaStreamCreateWithFlags(&sS, cudaStreamNonBlocking);
        cudaStreamCreateWithFlags(&s2, cudaStreamNonBlocking);
        cudaEventCreateWithFlags(&eF,    cudaEventDisableTiming);
        cudaEventCreateWithFlags(&eQ0,   cudaEventDisableTiming);
        cudaEventCreateWithFlags(&eAsg,  cudaEventDisableTiming);
        cudaEventCreateWithFlags(&eNeigh,cudaEventDisableTiming);
        cudaEventCreateWithFlags(&eNSpl, cudaEventDisableTiming);
        cudaEventCreateWithFlags(&eNormB,cudaEventDisableTiming);
        cudaEventCreateWithFlags(&eSp,   cudaEventDisableTiming);
        cudaEventCreateWithFlags(&eJoin, cudaEventDisableTiming);
    }
    cudaStream_t s0 = 0;

    // ======== FORK ========
    cudaEventRecord(eF, s0);
    cudaStreamWaitEvent(sS, eF, 0);
    cudaStreamWaitEvent(s2, eF, 0);

    // ---- sS: initial softmax (only needs unary), then full spatial chain ----
    softmax0K<<<gridFor(NPIX,B), B, 0, sS>>>(unary);
    cudaEventRecord(eQ0, sS);

    initHashK<DSP><<<gridFor(HSSZ,B), B, 0, sS>>>();
    buildK<DSP><<<gridFor(NPIX,B), B, 0, sS>>>(image);
    gZero<<<gridFor(NPIX,B), B, 0, sS>>>(gptr->pixCntS, NPIX);
    countMinK<DSP><<<gridFor(HSSZ,B), B, 0, sS>>>();
    gScanA<<<NPIX/256, 256, 0, sS>>>(gptr->pixCntS, gptr->pixStartS, gptr->pixBsumS, NPIX);
    gScanB<<<1, 1024, 0, sS>>>(gptr->pixBsumS, NPIX/256, &gptr->countS);
    gScanC<<<NPIX/256, 256, 0, sS>>>(gptr->pixStartS, gptr->pixFillS, gptr->pixBsumS, NPIX);
    assignOrdK<DSP><<<gridFor(HSSZ,B), B, 0, sS>>>();
    osRemapK<DSP><<<gridFor(NPIX*(DSP+1),B), B, 0, sS>>>();
    initNN2K<DSP><<<gridFor((long long)(DSP+1)*MSP,B), B, 0, sS>>>();
    neighK<DSP><<<gridFor(MSP,B), B, 0, sS>>>();
    gZero<<<gridFor(MSP,B), B, 0, sS>>>(gptr->cntS, MSP);
    countRowsK<DSP><<<gridFor(NPIX*(DSP+1),B), B, 0, sS>>>();
    gScanA<<<MSP/256, 256, 0, sS>>>(gptr->cntS, gptr->startS, gptr->bsumS, MSP);
    gScanB<<<1, 1024, 0, sS>>>(gptr->bsumS, MSP/256, nullptr);
    gScanC<<<MSP/256, 256, 0, sS>>>(gptr->startS, gptr->fillS, gptr->bsumS, MSP);
    fillK<DSP><<<gridFor(NPIX*(DSP+1),B), B, 0, sS>>>();
    splatNCsrK<DSP><<<SG, B, 0, sS>>>();
    blurN2K<DSP><<<SG, B, 0, sS>>>(0, 1, 0);
    blurNK <DSP><<<SG, B, 0, sS>>>(2, 1);
    sliceNormK<DSP><<<gridFor(NPIX,B), B, 0, sS>>>(ALPHA_S, 0);
    // iteration-1 spatial filter (Q0 already on sS)
    splatCsrSK<<<SG, B, 0, sS>>>();
    blur2SK<<<SG, B, 0, sS>>>(0, 1, 0);
    blurSK <<<SG, B, 0, sS>>>(2, 1);
    cudaEventRecord(eSp, sS);

    // ---- s0: bilateral mainline;  s2: bilateral helper ----
    initHashK<DBIL><<<gridFor(HBSZ,B), B, 0, s0>>>();
    buildK<DBIL><<<gridFor(NPIX,B), B, 0, s0>>>(image);
    gZero<<<gridFor(NPIX,B), B, 0, s0>>>(gptr->pixCntB, NPIX);
    countMinK<DBIL><<<gridFor(HBSZ,B), B, 0, s0>>>();
    gScanA<<<NPIX/256, 256, 0, s0>>>(gptr->pixCntB, gptr->pixStartB, gptr->pixBsumB, NPIX);
    gScanB<<<1, 1024, 0, s0>>>(gptr->pixBsumB, NPIX/256, &gptr->countB);
    gScanC<<<NPIX/256, 256, 0, s0>>>(gptr->pixStartB, gptr->pixFillB, gptr->pixBsumB, NPIX);
    assignOrdK<DBIL><<<gridFor(HBSZ,B), B, 0, s0>>>();
    cudaEventRecord(eAsg, s0);

    // s2: neighbor tables, concurrent with s0's CSR chain
    cudaStreamWaitEvent(s2, eAsg, 0);
    initNN2K<DBIL><<<gridFor((long long)(DBIL+1)*MBIL,B), B, 0, s2>>>();
    neighK<DBIL><<<gridFor(MBIL,B), B, 0, s2>>>();
    cudaEventRecord(eNeigh, s2);

    // s0: osRemap + CSR + norm splat
    osRemapK<DBIL><<<gridFor(NPIX*(DBIL+1),B), B, 0, s0>>>();
    gZero<<<gridFor(MBIL,B), B, 0, s0>>>(gptr->cntB, MBIL);
    countRowsK<DBIL><<<gridFor(NPIX*(DBIL+1),B), B, 0, s0>>>();
    gScanA<<<MBIL/256, 256, 0, s0>>>(gptr->cntB, gptr->startB, gptr->bsumB, MBIL);
    gScanB<<<1, 1024, 0, s0>>>(gptr->bsumB, MBIL/256, nullptr);
    gScanC<<<MBIL/256, 256, 0, s0>>>(gptr->startB, gptr->fillB, gptr->bsumB, MBIL);
    fillK<DBIL><<<gridFor(NPIX*(DBIL+1),B), B, 0, s0>>>();
    splatNCsrK<DBIL><<<gridFor(MBIL,B), B, 0, s0>>>();
    cudaEventRecord(eNSpl, s0);

    // s2: norm blurs (need neighK + norm splat), concurrent with iter-1 splat
    cudaStreamWaitEvent(s2, eNSpl, 0);
    blurN2K<DBIL><<<gridFor(MBIL,B), B, 0, s2>>>(0, 1, 0);
    blurN2K<DBIL><<<gridFor(MBIL,B), B, 0, s2>>>(2, 3, 1);
    blurN2K<DBIL><<<gridFor(MBIL,B), B, 0, s2>>>(4, 5, 0);
    sliceNormK<DBIL><<<gridFor(NPIX,B), B, 0, s2>>>(ALPHA_B, 1);
    cudaEventRecord(eNormB, s2);

    // s0: iteration-1 bilateral filter (splat needs Q0 + CSR; blur needs neighK)
    cudaStreamWaitEvent(s0, eQ0, 0);
    splatCsrBK<<<gridFor(MBIL,B), B, 0, s0>>>();
    cudaStreamWaitEvent(s0, eNeigh, 0);
    blur2BK<<<gridFor(2ll*MBIL*SEGW,B), B, 0, s0>>>(0, 1, 0);
    blur2BK<<<gridFor(2ll*MBIL*SEGW,B), B, 0, s0>>>(2, 3, 1);
    blur2BK<<<gridFor(2ll*MBIL*SEGW,B), B, 0, s0>>>(4, 5, 0);

    // join: slice needs spatial chain (eSp) + bilateral norms (eNormB)
    cudaStreamWaitEvent(s0, eSp, 0);
    cudaStreamWaitEvent(s0, eNormB, 0);
    sliceSoftmaxK<<<gridFor(NPIX,B), B, 0, s0>>>(
        unary, out, 0, WB*ALPHA_B, WSPA*ALPHA_S);

    // ---- iterations 2..5 ----
    for (int it=1; it<5; ++it){
        cudaEventRecord(eF, s0);
        cudaStreamWaitEvent(sS, eF, 0);

        splatCsrBK<<<gridFor(MBIL,B), B, 0, s0>>>();
        blur2BK<<<gridFor(2ll*MBIL*SEGW,B), B, 0, s0>>>(0, 1, 0);
        blur2BK<<<gridFor(2ll*MBIL*SEGW,B), B, 0, s0>>>(2, 3, 1);
        blur2BK<<<gridFor(2ll*MBIL*SEGW,B), B, 0, s0>>>(4, 5, 0);

        splatCsrSK<<<SG, B, 0, sS>>>();
        blur2SK<<<SG, B, 0, sS>>>(0, 1, 0);
        blurSK <<<SG, B, 0, sS>>>(2, 1);

        cudaEventRecord(eJoin, sS);
        cudaStreamWaitEvent(s0, eJoin, 0);

        sliceSoftmaxK<<<gridFor(NPIX,B), B, 0, s0>>>(
            unary, out, (it==4) ? 1 : 0,
            WB*ALPHA_B, WSPA*ALPHA_S);
    }
}

// round 17
// speedup vs baseline: 1.0547x; 1.0071x over previous
#include <cuda_runtime.h>
#include <cstdint>
#include <math.h>

// ----------------------------------------------------------------------------
// DenseCRF mean-field, permutohedral lattice. Round 17 = champion (651.3us:
// R10 + dead-Q-write-skip in final slice) + ONE provably-work-removing tweak:
// initNN2K bounds its writes by the live row count (entries with m >= count
// are never read by neighK/blur), shortening the exposed s2 init->neigh path.
// ----------------------------------------------------------------------------

#define HH 320
#define WW 320
#define NPIX (HH*WW)                 // 102400
#define NC 21
#define NCP 24
#define NQ4 6
#define SEGW 3
#define DBIL 5
#define DSP 2
#define MBIL (NPIX*(DBIL+1))         // 614400
#define MSP  (NPIX*(DSP+1))          // 307200
#define HBSZ (1u<<20)
#define HSSZ (1u<<17)
#define EMPTYK 0xFFFFFFFFFFFFFFFFULL

struct Globals {
    unsigned long long hkeyB[HBSZ];
    int                hidxB[HBSZ];
    int                hminB[HBSZ];
    unsigned long long hkeyS[HSSZ];
    int                hidxS[HSSZ];
    int                hminS[HSSZ];
    int countB, countS, pad_[2];
    unsigned long long ukeyB[MBIL];
    unsigned long long ukeyS[MSP];
    int   osB[NPIX*(DBIL+1)];
    float wsB[NPIX*(DBIL+1)];
    int   osS[NPIX*(DSP+1)];
    float wsS[NPIX*(DSP+1)];
    int2 nnB[(DBIL+1)*MBIL];
    int2 nnS[(DSP+1)*MSP];
    int pixCntB[NPIX], pixStartB[NPIX], pixFillB[NPIX], pixBsumB[512];
    int pixCntS[NPIX], pixStartS[NPIX], pixFillS[NPIX], pixBsumS[512];
    int   cntB[MBIL], startB[MBIL], fillB[MBIL];
    int   cntS[MSP],  startS[MSP],  fillS[MSP];
    int   bsumB[4096], bsumS[4096];
    int2  entB[NPIX*(DBIL+1)];
    int2  entS[NPIX*(DSP+1)];
    float4 bufB0[2ll*MBIL*SEGW];
    float4 bufB1[2ll*MBIL*SEGW];
    float4 bufS0[(long long)MSP*NQ4];
    float4 bufS1[(long long)MSP*NQ4];
    float nbuf0[MBIL];
    float nbuf1[MBIL];
    float nbufS0[MSP];
    float nbufS1[MSP];
    float normB[NPIX];
    float normS[NPIX];
    float4 Q[NPIX*NQ4];
};
__device__ Globals G;

// ---------------- selectors --------------------------------------------------
template<int D> __device__ __forceinline__ unsigned long long* HK()   { return (D==DBIL)? G.hkeyB : G.hkeyS; }
template<int D> __device__ __forceinline__ int*                HI()   { return (D==DBIL)? G.hidxB : G.hidxS; }
template<int D> __device__ __forceinline__ int*                HMIN() { return (D==DBIL)? G.hminB : G.hminS; }
template<int D> __device__ __forceinline__ int*                CNTp() { return (D==DBIL)? &G.countB : &G.countS; }
template<int D> __device__ __forceinline__ unsigned long long* UK()   { return (D==DBIL)? G.ukeyB : G.ukeyS; }
template<int D> __device__ __forceinline__ int*                OS()   { return (D==DBIL)? G.osB : G.osS; }
template<int D> __device__ __forceinline__ float*              WSp()  { return (D==DBIL)? G.wsB : G.wsS; }
template<int D> __device__ __forceinline__ int2*               NN()   { return (D==DBIL)? G.nnB : G.nnS; }
template<int D> __device__ __forceinline__ int*                RCNT() { return (D==DBIL)? G.cntB : G.cntS; }
template<int D> __device__ __forceinline__ int*                RST()  { return (D==DBIL)? G.startB : G.startS; }
template<int D> __device__ __forceinline__ int*                RFIL() { return (D==DBIL)? G.fillB : G.fillS; }
template<int D> __device__ __forceinline__ int2*               ENT()  { return (D==DBIL)? G.entB : G.entS; }
template<int D> __device__ __forceinline__ int*                PCNT() { return (D==DBIL)? G.pixCntB : G.pixCntS; }
template<int D> __device__ __forceinline__ int*                PFIL() { return (D==DBIL)? G.pixFillB : G.pixFillS; }
template<int D> __device__ __forceinline__ float*              NB0()  { return (D==DBIL)? G.nbuf0 : G.nbufS0; }
template<int D> __device__ __forceinline__ float*              NB1()  { return (D==DBIL)? G.nbuf1 : G.nbufS1; }
template<int D> __host__ __device__ constexpr unsigned int HMSK(){ return (D==DBIL)? (HBSZ-1u) : (HSSZ-1u); }
template<int D> __host__ __device__ constexpr unsigned int HSZ (){ return (D==DBIL)? HBSZ : HSSZ; }
template<int D> __host__ __device__ constexpr int          MMAX(){ return (D==DBIL)? MBIL : MSP; }

// ---------------- hash -------------------------------------------------------
__device__ __forceinline__ unsigned int hmix(unsigned long long x, unsigned int mask){
    x ^= x >> 33; x *= 0xff51afd7ed558ccdULL;
    x ^= x >> 33; x *= 0xc4ceb9fe1a85ec53ULL;
    x ^= x >> 33;
    return (unsigned int)x & mask;
}
__device__ __forceinline__ unsigned int hinsert(unsigned long long* hk, unsigned int mask,
                                                unsigned long long key){
    unsigned int s = hmix(key, mask);
    while (true){
        unsigned long long prev = atomicCAS(&hk[s], EMPTYK, key);
        if (prev == EMPTYK || prev == key) return s;
        s = (s+1) & mask;
    }
}
__device__ __forceinline__ int hlookup(const unsigned long long* hk, const int* hi,
                                       unsigned int mask, unsigned long long key){
    unsigned int s = hmix(key, mask);
    while (true){
        unsigned long long k = hk[s];
        if (k == key)    return hi[s];
        if (k == EMPTYK) return -1;
        s = (s+1) & mask;
    }
}

// ---------------- lattice build ----------------------------------------------
template<int D>
__global__ void initHashK(){
    unsigned int s = blockIdx.x*blockDim.x + threadIdx.x;
    if (s < HSZ<D>()){ HK<D>()[s] = EMPTYK; HMIN<D>()[s] = 0x7FFFFFFF; }
    if (s == 0) *CNTp<D>() = 0;
}

template<int D>
__global__ void buildK(const float* __restrict__ image){
    int i = blockIdx.x*blockDim.x + threadIdx.x;
    if (i >= NPIX) return;
    float f[D];
    float x = (float)(i % WW), y = (float)(i / WW);
    if constexpr (D == DBIL){
        f[0] = x / 80.0f;  f[1] = y / 80.0f;
        f[2] = image[i*3+0] / 13.0f;
        f[3] = image[i*3+1] / 13.0f;
        f[4] = image[i*3+2] / 13.0f;
    } else {
        f[0] = x / 3.0f;   f[1] = y / 3.0f;
    }
    float cf[D];
    #pragma unroll
    for (int k=0;k<D;k++){
        double sc = sqrt(2.0/3.0) * (double)(D+1) / sqrt((double)((k+1)*(k+2)));
        cf[k] = f[k] * (float)sc;
    }
    float suf[D];
    { float s=0.f; for (int k=D-1;k>=0;k--){ s += cf[k]; suf[k]=s; } }
    float el[D+1];
    el[0] = suf[0];
    #pragma unroll
    for (int k=1;k<=D;k++){
        float t = (k<D) ? suf[k] : 0.0f;
        el[k] = t - (float)k * cf[k-1];
    }
    const float down = 1.0f/(float)(D+1);
    float rem0[D+1]; int rank[D+1]; int ssum=0;
    #pragma unroll
    for (int k=0;k<=D;k++){
        float rd = rintf(el[k]*down);
        rem0[k] = rd * (float)(D+1);
        ssum += (int)rd;
    }
    float diff[D+1];
    #pragma unroll
    for (int k=0;k<=D;k++) diff[k] = el[k] - rem0[k];
    #pragma unroll
    for (int a=0;a<=D;a++){
        int r = 0;
        #pragma unroll
        for (int b=0;b<=D;b++)
            if (diff[b] > diff[a] || (diff[b] == diff[a] && b < a)) r++;
        rank[a] = r + ssum;
    }
    #pragma unroll
    for (int k=0;k<=D;k++){
        if (rank[k] < 0)      { rank[k] += D+1; rem0[k] += (float)(D+1); }
        else if (rank[k] > D) { rank[k] -= D+1; rem0[k] -= (float)(D+1); }
    }
    float bb[D+2];
    #pragma unroll
    for (int k=0;k<D+2;k++) bb[k]=0.f;
    #pragma unroll
    for (int k=0;k<=D;k++){
        float v = (el[k]-rem0[k]) * down;
        bb[D   - rank[k]] += v;
        bb[D+1 - rank[k]] -= v;
    }
    bb[0] += 1.0f + bb[D+1];
    int key0[D];
    #pragma unroll
    for (int k=0;k<D;k++) key0[k] = (int)lrintf(rem0[k]);
    unsigned long long* hk = HK<D>();
    int* hmn = HMIN<D>();
    const unsigned int mask = HMSK<D>();
    #pragma unroll
    for (int r=0;r<=D;r++){
        unsigned long long pk = 0;
        #pragma unroll
        for (int k=0;k<D;k++){
            int canon = (rank[k] < D+1-r) ? r : r-(D+1);
            pk |= ((unsigned long long)(unsigned int)(key0[k]+canon+2048) & 0xFFFULL) << (12*k);
        }
        WSp<D>()[i*(D+1)+r] = bb[r];
        unsigned int slot = hinsert(hk, mask, pk);
        OS<D>()[i*(D+1)+r] = (int)slot;
        atomicMin(&hmn[slot], i);
    }
}

// ---- generic scan helpers ---------------------------------------------------
__global__ void gZero(int* a, int n){
    int t = blockIdx.x*blockDim.x + threadIdx.x;
    if (t < n) a[t] = 0;
}
__global__ void gScanA(const int* __restrict__ cnt, int* __restrict__ st,
                       int* __restrict__ bsum, int n){
    __shared__ int sh[256];
    int t = threadIdx.x;
    int g = blockIdx.x*256 + t;
    int v = (g < n) ? cnt[g] : 0;
    sh[t] = v; __syncthreads();
    #pragma unroll
    for (int o=1;o<256;o<<=1){
        int x = (t>=o) ? sh[t-o] : 0;
        __syncthreads();
        sh[t] += x;
        __syncthreads();
    }
    if (g < n) st[g] = sh[t] - v;
    if (t == 255) bsum[blockIdx.x] = sh[255];
}
__global__ void gScanB(int* __restrict__ bsum, int nb, int* total){
    __shared__ int sh[1024];
    int t = threadIdx.x;
    int carry = 0;
    for (int base=0; base<nb; base+=1024){
        int v = (base+t < nb) ? bsum[base+t] : 0;
        sh[t] = v; __syncthreads();
        for (int o=1;o<1024;o<<=1){
            int x = (t>=o) ? sh[t-o] : 0;
            __syncthreads();
            sh[t] += x;
            __syncthreads();
        }
        int tot = sh[1023];
        if (base+t < nb) bsum[base+t] = sh[t] - v + carry;
        __syncthreads();
        carry += tot;
    }
    if (t == 0 && total) *total = carry;
}
__global__ void gScanC(int* __restrict__ st, int* __restrict__ fill,
                       const int* __restrict__ bsum, int n){
    int g = blockIdx.x*256 + threadIdx.x;
    if (g >= n) return;
    int s = st[g] + bsum[g >> 8];
    st[g] = s;
    if (fill) fill[g] = s;
}

template<int D>
__global__ void countMinK(){
    unsigned int s = blockIdx.x*blockDim.x + threadIdx.x;
    if (s >= HSZ<D>()) return;
    if (HK<D>()[s] != EMPTYK)
        atomicAdd(&PCNT<D>()[HMIN<D>()[s]], 1);
}
template<int D>
__global__ void assignOrdK(){
    unsigned int s = blockIdx.x*blockDim.x + threadIdx.x;
    if (s >= HSZ<D>()) return;
    unsigned long long k = HK<D>()[s];
    if (k == EMPTYK) return;
    int idx = atomicAdd(&PFIL<D>()[HMIN<D>()[s]], 1);
    HI<D>()[s] = idx;
    UK<D>()[idx] = k;
}

template<int D>
__global__ void osRemapK(){
    int t = blockIdx.x*blockDim.x + threadIdx.x;
    if (t >= NPIX*(D+1)) return;
    OS<D>()[t] = HI<D>()[OS<D>()[t]];
}

// init only the LIVE slices of the neighbor table: entries j*MMAX+m with
// m >= count are never read by neighK or any blur.
template<int D>
__global__ void initNN2K(){
    int M = *CNTp<D>();
    long long total = (long long)(D+1)*M;
    int2* nn = NN<D>();
    for (long long t = (long long)blockIdx.x*blockDim.x + threadIdx.x;
         t < total; t += (long long)gridDim.x*blockDim.x){
        int j = (int)(t / M);
        int m = (int)(t - (long long)j*M);
        nn[(size_t)j*MMAX<D>() + m] = make_int2(-1, -1);
    }
}

template<int D>
__global__ void neighK(){
    int m = blockIdx.x*blockDim.x + threadIdx.x;
    if (m >= *CNTp<D>()) return;
    unsigned long long k = UK<D>()[m];
    int c[D];
    #pragma unroll
    for (int t=0;t<D;t++) c[t] = (int)((k >> (12*t)) & 0xFFF) - 2048;
    unsigned long long* hk = HK<D>(); int* hi = HI<D>();
    const unsigned int mask = HMSK<D>();
    int* nnraw = (int*)NN<D>();
    #pragma unroll
    for (int j=0;j<=D;j++){
        unsigned long long p1=0;
        #pragma unroll
        for (int t=0;t<D;t++){
            int a1 = c[t]-1 + ((t==j)?(D+1):0);
            p1 |= ((unsigned long long)(unsigned int)(a1+2048) & 0xFFFULL) << (12*t);
        }
        int i1 = hlookup(hk, hi, mask, p1);
        long long slot = (long long)j*MMAX<D>() + m;
        nnraw[2*slot] = i1;
        if (i1 >= 0)
            nnraw[2*((long long)j*MMAX<D>() + i1) + 1] = m;
    }
}

// ---------------- CSR build --------------------------------------------------
template<int D>
__global__ void countRowsK(){
    int t = blockIdx.x*blockDim.x + threadIdx.x;
    if (t >= NPIX*(D+1)) return;
    atomicAdd(&RCNT<D>()[OS<D>()[t]], 1);
}
template<int D>
__global__ void fillK(){
    int t = blockIdx.x*blockDim.x + threadIdx.x;
    if (t >= NPIX*(D+1)) return;
    int m = OS<D>()[t];
    int p = atomicAdd(&RFIL<D>()[m], 1);
    ENT<D>()[p] = make_int2(t / (D+1), __float_as_int(WSp<D>()[t]));
}

// ---------------- norm filter ------------------------------------------------
template<int D>
__global__ void splatNCsrK(){
    for (int m = blockIdx.x*blockDim.x + threadIdx.x; m < *CNTp<D>();
         m += gridDim.x*blockDim.x){
        int s = RST<D>()[m], e = s + RCNT<D>()[m];
        float acc = 0.f;
        for (int k=s;k<e;k++) acc += __int_as_float(ENT<D>()[k].y);
        NB0<D>()[m] = acc;
    }
}
template<int D>
__global__ void blurN2K(int j1, int j2, int p){
    int M = *CNTp<D>();
    const float* in = p ? NB1<D>() : NB0<D>();
    float*      out = p ? NB0<D>() : NB1<D>();
    const int2* na = NN<D>() + (size_t)j1*MMAX<D>();
    const int2* nb = NN<D>() + (size_t)j2*MMAX<D>();
    for (int m = blockIdx.x*blockDim.x + threadIdx.x; m < M;
         m += gridDim.x*blockDim.x){
        int2 A = na[m]; int2 B = nb[m];
        float r = in[m];
        {
            float acc = 0.f;
            if (A.x >= 0) acc += in[A.x];
            if (A.y >= 0) acc += in[A.y];
            r += 0.5f*acc;
        }
        float accB = 0.f;
        if (B.x >= 0){
            float t = in[B.x];
            int2 c = na[B.x];
            float cc = 0.f;
            if (c.x >= 0) cc += in[c.x];
            if (c.y >= 0) cc += in[c.y];
            accB += t + 0.5f*cc;
        }
        if (B.y >= 0){
            float t = in[B.y];
            int2 c = na[B.y];
            float cc = 0.f;
            if (c.x >= 0) cc += in[c.x];
            if (c.y >= 0) cc += in[c.y];
            accB += t + 0.5f*cc;
        }
        out[m] = r + 0.5f*accB;
    }
}
template<int D>
__global__ void blurNK(int j, int p){
    int M = *CNTp<D>();
    const float* in = p ? NB1<D>() : NB0<D>();
    float*      out = p ? NB0<D>() : NB1<D>();
    for (int m = blockIdx.x*blockDim.x + threadIdx.x; m < M;
         m += gridDim.x*blockDim.x){
        int2 a = NN<D>()[j*MMAX<D>()+m];
        float va = (a.x >= 0) ? in[a.x] : 0.f;
        float vb = (a.y >= 0) ? in[a.y] : 0.f;
        out[m] = in[m] + 0.5f*(va + vb);
    }
}
template<int D>
__global__ void sliceNormK(float alpha, int p){
    int i = blockIdx.x*blockDim.x + threadIdx.x;
    if (i >= NPIX) return;
    const float* nb = p ? NB1<D>() : NB0<D>();
    const int*   os = OS<D>(); const float* ws = WSp<D>();
    float s = 0.f;
    #pragma unroll
    for (int j=0;j<=D;j++) s += ws[i*(D+1)+j] * nb[os[i*(D+1)+j]];
    float* nrm = (D==DBIL) ? G.normB : G.normS;
    nrm[i] = alpha * s + 1e-20f;
}

// ---------------- hot-loop kernels -------------------------------------------
__device__ __forceinline__ float4 f4fma(float4 a, float s, float4 b){
    return make_float4(fmaf(a.x,s,b.x), fmaf(a.y,s,b.y), fmaf(a.z,s,b.z), fmaf(a.w,s,b.w));
}
__device__ __forceinline__ float4 f4add(float4 a, float4 b){
    return make_float4(a.x+b.x, a.y+b.y, a.z+b.z, a.w+b.w);
}

__global__ void splatCsrBK(){
    int m = blockIdx.x*blockDim.x + threadIdx.x;
    if (m >= G.countB) return;
    int s = G.startB[m], e = s + G.cntB[m];
    float4 a0=make_float4(0,0,0,0), a1=a0, a2=a0, a3=a0, a4=a0, a5=a0;
    for (int k=s;k<e;k++){
        int2 ent = G.entB[k];
        float w = __int_as_float(ent.y);
        const float4* q = &G.Q[ent.x*NQ4];
        a0 = f4fma(q[0], w, a0);
        a1 = f4fma(q[1], w, a1);
        a2 = f4fma(q[2], w, a2);
        a3 = f4fma(q[3], w, a3);
        a4 = f4fma(q[4], w, a4);
        a5 = f4fma(q[5], w, a5);
    }
    float4* s0 = &G.bufB0[(size_t)m*SEGW];
    s0[0]=a0; s0[1]=a1; s0[2]=a2;
    float4* s1 = &G.bufB0[(size_t)MBIL*SEGW + (size_t)m*SEGW];
    s1[0]=a3; s1[1]=a4; s1[2]=a5;
}
__global__ void splatCsrSK(){
    int M = G.countS;
    for (int m = blockIdx.x*blockDim.x + threadIdx.x; m < M;
         m += gridDim.x*blockDim.x){
        int s = G.startS[m], e = s + G.cntS[m];
        float4 a[NQ4];
        #pragma unroll
        for (int q=0;q<NQ4;q++) a[q]=make_float4(0,0,0,0);
        for (int k=s;k<e;k++){
            int2 ent = G.entS[k];
            float w = __int_as_float(ent.y);
            const float4* q = &G.Q[ent.x*NQ4];
            #pragma unroll
            for (int qi=0;qi<NQ4;qi++) a[qi] = f4fma(q[qi], w, a[qi]);
        }
        float4* o = &G.bufS0[(size_t)m*NQ4];
        #pragma unroll
        for (int qi=0;qi<NQ4;qi++) o[qi]=a[qi];
    }
}

__global__ void blur2BK(int j1, int j2, int p){
    long long tid = (long long)blockIdx.x*blockDim.x + threadIdx.x;
    int M = G.countB;
    long long perseg = (long long)M*SEGW;
    int seg = (tid >= perseg) ? 1 : 0;
    long long rem = tid - (long long)seg*perseg;
    int m = (int)(rem / SEGW), q = (int)(rem % SEGW);
    if (m >= M) return;
    size_t base = (size_t)seg*MBIL*SEGW;
    const float4* __restrict__ in  = (p ? G.bufB1 : G.bufB0) + base;
    float4*       __restrict__ out = (p ? G.bufB0 : G.bufB1) + base;
    const int2* __restrict__ na = G.nnB + (size_t)j1*MBIL;
    const int2* __restrict__ nb = G.nnB + (size_t)j2*MBIL;

    int2 A = na[m];
    int2 B = nb[m];

    float4 r = in[(size_t)m*SEGW+q];
    {
        float4 acc = make_float4(0,0,0,0);
        if (A.x >= 0) acc = in[(size_t)A.x*SEGW+q];
        if (A.y >= 0) acc = f4add(acc, in[(size_t)A.y*SEGW+q]);
        r = f4fma(acc, 0.5f, r);
    }
    float4 accB = make_float4(0,0,0,0);
    if (B.x >= 0){
        float4 t = in[(size_t)B.x*SEGW+q];
        int2 c = na[B.x];
        float4 cc = make_float4(0,0,0,0);
        if (c.x >= 0) cc = in[(size_t)c.x*SEGW+q];
        if (c.y >= 0) cc = f4add(cc, in[(size_t)c.y*SEGW+q]);
        accB = f4fma(cc, 0.5f, t);
    }
    if (B.y >= 0){
        float4 t = in[(size_t)B.y*SEGW+q];
        int2 c = na[B.y];
        float4 cc = make_float4(0,0,0,0);
        if (c.x >= 0) cc = in[(size_t)c.x*SEGW+q];
        if (c.y >= 0) cc = f4add(cc, in[(size_t)c.y*SEGW+q]);
        accB = f4add(accB, f4fma(cc, 0.5f, t));
    }
    out[(size_t)m*SEGW+q] = f4fma(accB, 0.5f, r);
}

__global__ void blur2SK(int j1, int j2, int p){
    int M = G.countS;
    const float4* __restrict__ in  = p ? G.bufS1 : G.bufS0;
    float4*       __restrict__ out = p ? G.bufS0 : G.bufS1;
    const int2* __restrict__ na = G.nnS + (size_t)j1*MSP;
    const int2* __restrict__ nb = G.nnS + (size_t)j2*MSP;
    long long total = (long long)M*NQ4;
    for (long long tid = (long long)blockIdx.x*blockDim.x + threadIdx.x;
         tid < total; tid += (long long)gridDim.x*blockDim.x){
        int m = (int)(tid / NQ4), q = (int)(tid % NQ4);
        int2 A = na[m];
        int2 B = nb[m];
        float4 r = in[(size_t)m*NQ4+q];
        {
            float4 acc = make_float4(0,0,0,0);
            if (A.x >= 0) acc = in[(size_t)A.x*NQ4+q];
            if (A.y >= 0) acc = f4add(acc, in[(size_t)A.y*NQ4+q]);
            r = f4fma(acc, 0.5f, r);
        }
        float4 accB = make_float4(0,0,0,0);
        if (B.x >= 0){
            float4 t = in[(size_t)B.x*NQ4+q];
            int2 c = na[B.x];
            float4 cc = make_float4(0,0,0,0);
            if (c.x >= 0) cc = in[(size_t)c.x*NQ4+q];
            if (c.y >= 0) cc = f4add(cc, in[(size_t)c.y*NQ4+q]);
            accB = f4fma(cc, 0.5f, t);
        }
        if (B.y >= 0){
            float4 t = in[(size_t)B.y*NQ4+q];
            int2 c = na[B.y];
            float4 cc = make_float4(0,0,0,0);
            if (c.x >= 0) cc = in[(size_t)c.x*NQ4+q];
            if (c.y >= 0) cc = f4add(cc, in[(size_t)c.y*NQ4+q]);
            accB = f4add(accB, f4fma(cc, 0.5f, t));
        }
        out[(size_t)m*NQ4+q] = f4fma(accB, 0.5f, r);
    }
}

__global__ void blurSK(int j, int p){
    int M = G.countS;
    const float4* __restrict__ in  = p ? G.bufS1 : G.bufS0;
    float4*       __restrict__ out = p ? G.bufS0 : G.bufS1;
    long long total = (long long)M*NQ4;
    for (long long tid = (long long)blockIdx.x*blockDim.x + threadIdx.x;
         tid < total; tid += (long long)gridDim.x*blockDim.x){
        int m = (int)(tid / NQ4), q = (int)(tid % NQ4);
        int2 a = G.nnS[j*MSP+m];
        float4 self = in[(size_t)m*NQ4+q];
        float4 acc = make_float4(0.f,0.f,0.f,0.f);
        if (a.x >= 0) acc = in[(size_t)a.x*NQ4+q];
        if (a.y >= 0) acc = f4add(acc, in[(size_t)a.y*NQ4+q]);
        out[(size_t)m*NQ4+q] = f4fma(acc, 0.5f, self);
    }
}

__global__ void sliceSoftmaxK(const float* __restrict__ U,
                              float* __restrict__ out, int writeOut,
                              float fBmul, float fSmul){
    int i = blockIdx.x*blockDim.x + threadIdx.x;
    if (i >= NPIX) return;

    int   osb[DBIL+1]; float wsb[DBIL+1];
    #pragma unroll
    for (int j=0;j<=DBIL;j++){
        osb[j] = G.osB[i*(DBIL+1)+j];
        wsb[j] = G.wsB[i*(DBIL+1)+j];
    }
    int   oss[DSP+1]; float wss[DSP+1];
    #pragma unroll
    for (int j=0;j<=DSP;j++){
        oss[j] = G.osS[i*(DSP+1)+j];
        wss[j] = G.wsS[i*(DSP+1)+j];
    }
    float fB = fBmul / G.normB[i];
    float fS = fSmul / G.normS[i];

    const float4* __restrict__ bB = G.bufB1;
    const float4* __restrict__ bS = G.bufS0;

    float lg[NCP];
    float mx = -3.4e38f;
    #pragma unroll
    for (int q=0;q<NQ4;q++){
        int seg = (q < SEGW) ? 0 : 1;
        int qq  = q - seg*SEGW;
        size_t base = (size_t)seg*MBIL*SEGW + qq;
        float4 sB = make_float4(0.f,0.f,0.f,0.f);
        #pragma unroll
        for (int j=0;j<=DBIL;j++)
            sB = f4fma(bB[base + (size_t)osb[j]*SEGW], wsb[j], sB);
        float4 sS = make_float4(0.f,0.f,0.f,0.f);
        #pragma unroll
        for (int j=0;j<=DSP;j++)
            sS = f4fma(bS[(size_t)oss[j]*NQ4+q], wss[j], sS);
        #pragma unroll
        for (int k=0;k<4;k++){
            int ch = q*4+k;
            float m4 = (k==0)?(fB*sB.x+fS*sS.x):(k==1)?(fB*sB.y+fS*sS.y)
                     : (k==2)?(fB*sB.z+fS*sS.z):(fB*sB.w+fS*sS.w);
            float l = (ch < NC) ? (-U[i*NC+ch] + m4) : -3.4e38f;
            lg[q*4+k] = l;
            mx = fmaxf(mx, l);
        }
    }
    float sum = 0.f;
    #pragma unroll
    for (int c=0;c<NCP;c++){
        float e = (lg[c] > -1e37f) ? expf(lg[c]-mx) : 0.f;
        lg[c] = e; sum += e;
    }
    float inv = 1.0f / sum;
    if (writeOut){
        // final iteration: Q is dead after this kernel — write only the output
        float* o = out + (long long)i*NC;
        #pragma unroll
        for (int c=0;c<NC;c++) o[c] = lg[c]*inv;
    } else {
        #pragma unroll
        for (int q=0;q<NQ4;q++){
            float4 qv = make_float4(lg[q*4+0]*inv, lg[q*4+1]*inv,
                                    lg[q*4+2]*inv, lg[q*4+3]*inv);
            G.Q[i*NQ4+q] = qv;
        }
    }
}

__global__ void softmax0K(const float* __restrict__ U){
    int i = blockIdx.x*blockDim.x + threadIdx.x;
    if (i >= NPIX) return;
    float t[NC];
    float mx = -3.4e38f;
    #pragma unroll
    for (int c=0;c<NC;c++){
        float l = -U[i*NC+c];
        t[c] = l; mx = fmaxf(mx, l);
    }
    float sum = 0.f;
    #pragma unroll
    for (int c=0;c<NC;c++){ float e = expf(t[c]-mx); t[c]=e; sum += e; }
    float inv = 1.0f / sum;
    float* q = (float*)&G.Q[i*NQ4];
    #pragma unroll
    for (int c=0;c<NC;c++) q[c] = t[c]*inv;
    #pragma unroll
    for (int c=NC;c<NCP;c++) q[c] = 0.f;
}

// ---------------- host -------------------------------------------------------
static inline unsigned int gridFor(long long n, int B){ return (unsigned int)((n + B - 1) / B); }

extern "C" void kernel_launch(void* const* d_in, const int* in_sizes, int n_in,
                              void* d_out, int out_size){
    const float* unary = nullptr;
    const float* image = nullptr;
    for (int k=0;k<n_in;k++){
        if      (in_sizes[k] == NPIX*NC) unary = (const float*)d_in[k];
        else if (in_sizes[k] == NPIX*3)  image = (const float*)d_in[k];
    }
    if (!unary || !image) return;
    float* out = (float*)d_out;
    const int B = 256;
    const int SG = 512;

    const float ALPHA_B = 32.0f/33.0f;
    const float ALPHA_S = 0.8f;
    const float WB = 10.0f, WSPA = 3.0f;

    static Globals* gptr = nullptr;
    static cudaStream_t sS = nullptr, s2 = nullptr;
    static cudaEvent_t eF=nullptr, eQ0=nullptr, eAsg=nullptr, eNeigh=nullptr,
                       eNSpl=nullptr, eNormB=nullptr, eSp=nullptr, eJoin=nullptr;
    if (!gptr){
        cudaGetSymbolAddress((void**)&gptr, G);
        cudaStreamCreateWithFlags(&sS, cudaStreamNonBlocking);
        cudaStreamCreateWithFlags(&s2, cudaStreamNonBlocking);
        cudaEventCreateWithFlags(&eF,    cudaEventDisableTiming);
        cudaEventCreateWithFlags(&eQ0,   cudaEventDisableTiming);
        cudaEventCreateWithFlags(&eAsg,  cudaEventDisableTiming);
        cudaEventCreateWithFlags(&eNeigh,cudaEventDisableTiming);
        cudaEventCreateWithFlags(&eNSpl, cudaEventDisableTiming);
        cudaEventCreateWithFlags(&eNormB,cudaEventDisableTiming);
        cudaEventCreateWithFlags(&eSp,   cudaEventDisableTiming);
        cudaEventCreateWithFlags(&eJoin, cudaEventDisableTiming);
    }
    cudaStream_t s0 = 0;

    // ======== FORK ========
    cudaEventRecord(eF, s0);
    cudaStreamWaitEvent(sS, eF, 0);
    cudaStreamWaitEvent(s2, eF, 0);

    // ---- sS: initial softmax (only needs unary), then full spatial chain ----
    softmax0K<<<gridFor(NPIX,B), B, 0, sS>>>(unary);
    cudaEventRecord(eQ0, sS);

    initHashK<DSP><<<gridFor(HSSZ,B), B, 0, sS>>>();
    buildK<DSP><<<gridFor(NPIX,B), B, 0, sS>>>(image);
    gZero<<<gridFor(NPIX,B), B, 0, sS>>>(gptr->pixCntS, NPIX);
    countMinK<DSP><<<gridFor(HSSZ,B), B, 0, sS>>>();
    gScanA<<<NPIX/256, 256, 0, sS>>>(gptr->pixCntS, gptr->pixStartS, gptr->pixBsumS, NPIX);
    gScanB<<<1, 1024, 0, sS>>>(gptr->pixBsumS, NPIX/256, &gptr->countS);
    gScanC<<<NPIX/256, 256, 0, sS>>>(gptr->pixStartS, gptr->pixFillS, gptr->pixBsumS, NPIX);
    assignOrdK<DSP><<<gridFor(HSSZ,B), B, 0, sS>>>();
    osRemapK<DSP><<<gridFor(NPIX*(DSP+1),B), B, 0, sS>>>();
    initNN2K<DSP><<<SG, B, 0, sS>>>();
    neighK<DSP><<<gridFor(MSP,B), B, 0, sS>>>();
    gZero<<<gridFor(MSP,B), B, 0, sS>>>(gptr->cntS, MSP);
    countRowsK<DSP><<<gridFor(NPIX*(DSP+1),B), B, 0, sS>>>();
    gScanA<<<MSP/256, 256, 0, sS>>>(gptr->cntS, gptr->startS, gptr->bsumS, MSP);
    gScanB<<<1, 1024, 0, sS>>>(gptr->bsumS, MSP/256, nullptr);
    gScanC<<<MSP/256, 256, 0, sS>>>(gptr->startS, gptr->fillS, gptr->bsumS, MSP);
    fillK<DSP><<<gridFor(NPIX*(DSP+1),B), B, 0, sS>>>();
    splatNCsrK<DSP><<<SG, B, 0, sS>>>();
    blurN2K<DSP><<<SG, B, 0, sS>>>(0, 1, 0);
    blurNK <DSP><<<SG, B, 0, sS>>>(2, 1);
    sliceNormK<DSP><<<gridFor(NPIX,B), B, 0, sS>>>(ALPHA_S, 0);
    // iteration-1 spatial filter (Q0 already on sS)
    splatCsrSK<<<SG, B, 0, sS>>>();
    blur2SK<<<SG, B, 0, sS>>>(0, 1, 0);
    blurSK <<<SG, B, 0, sS>>>(2, 1);
    cudaEventRecord(eSp, sS);

    // ---- s0: bilateral mainline;  s2: bilateral helper ----
    initHashK<DBIL><<<gridFor(HBSZ,B), B, 0, s0>>>();
    buildK<DBIL><<<gridFor(NPIX,B), B, 0, s0>>>(image);
    gZero<<<gridFor(NPIX,B), B, 0, s0>>>(gptr->pixCntB, NPIX);
    countMinK<DBIL><<<gridFor(HBSZ,B), B, 0, s0>>>();
    gScanA<<<NPIX/256, 256, 0, s0>>>(gptr->pixCntB, gptr->pixStartB, gptr->pixBsumB, NPIX);
    gScanB<<<1, 1024, 0, s0>>>(gptr->pixBsumB, NPIX/256, &gptr->countB);
    gScanC<<<NPIX/256, 256, 0, s0>>>(gptr->pixStartB, gptr->pixFillB, gptr->pixBsumB, NPIX);
    assignOrdK<DBIL><<<gridFor(HBSZ,B), B, 0, s0>>>();
    cudaEventRecord(eAsg, s0);

    // s2: neighbor tables, concurrent with s0's CSR chain
    cudaStreamWaitEvent(s2, eAsg, 0);
    initNN2K<DBIL><<<2048, B, 0, s2>>>();
    neighK<DBIL><<<gridFor(MBIL,B), B, 0, s2>>>();
    cudaEventRecord(eNeigh, s2);

    // s0: osRemap + CSR + norm splat
    osRemapK<DBIL><<<gridFor(NPIX*(DBIL+1),B), B, 0, s0>>>();
    gZero<<<gridFor(MBIL,B), B, 0, s0>>>(gptr->cntB, MBIL);
    countRowsK<DBIL><<<gridFor(NPIX*(DBIL+1),B), B, 0, s0>>>();
    gScanA<<<MBIL/256, 256, 0, s0>>>(gptr->cntB, gptr->startB, gptr->bsumB, MBIL);
    gScanB<<<1, 1024, 0, s0>>>(gptr->bsumB, MBIL/256, nullptr);
    gScanC<<<MBIL/256, 256, 0, s0>>>(gptr->startB, gptr->fillB, gptr->bsumB, MBIL);
    fillK<DBIL><<<gridFor(NPIX*(DBIL+1),B), B, 0, s0>>>();
    splatNCsrK<DBIL><<<gridFor(MBIL,B), B, 0, s0>>>();
    cudaEventRecord(eNSpl, s0);

    // s2: norm blurs (need neighK + norm splat), concurrent with iter-1 splat
    cudaStreamWaitEvent(s2, eNSpl, 0);
    blurN2K<DBIL><<<gridFor(MBIL,B), B, 0, s2>>>(0, 1, 0);
    blurN2K<DBIL><<<gridFor(MBIL,B), B, 0, s2>>>(2, 3, 1);
    blurN2K<DBIL><<<gridFor(MBIL,B), B, 0, s2>>>(4, 5, 0);
    sliceNormK<DBIL><<<gridFor(NPIX,B), B, 0, s2>>>(ALPHA_B, 1);
    cudaEventRecord(eNormB, s2);

    // s0: iteration-1 bilateral filter (splat needs Q0 + CSR; blur needs neighK)
    cudaStreamWaitEvent(s0, eQ0, 0);
    splatCsrBK<<<gridFor(MBIL,B), B, 0, s0>>>();
    cudaStreamWaitEvent(s0, eNeigh, 0);
    blur2BK<<<gridFor(2ll*MBIL*SEGW,B), B, 0, s0>>>(0, 1, 0);
    blur2BK<<<gridFor(2ll*MBIL*SEGW,B), B, 0, s0>>>(2, 3, 1);
    blur2BK<<<gridFor(2ll*MBIL*SEGW,B), B, 0, s0>>>(4, 5, 0);

    // join: slice needs spatial chain (eSp) + bilateral norms (eNormB)
    cudaStreamWaitEvent(s0, eSp, 0);
    cudaStreamWaitEvent(s0, eNormB, 0);
    sliceSoftmaxK<<<gridFor(NPIX,B), B, 0, s0>>>(
        unary, out, 0, WB*ALPHA_B, WSPA*ALPHA_S);

    // ---- iterations 2..5 ----
    for (int it=1; it<5; ++it){
        cudaEventRecord(eF, s0);
        cudaStreamWaitEvent(sS, eF, 0);

        splatCsrBK<<<gridFor(MBIL,B), B, 0, s0>>>();
        blur2BK<<<gridFor(2ll*MBIL*SEGW,B), B, 0, s0>>>(0, 1, 0);
        blur2BK<<<gridFor(2ll*MBIL*SEGW,B), B, 0, s0>>>(2, 3, 1);
        blur2BK<<<gridFor(2ll*MBIL*SEGW,B), B, 0, s0>>>(4, 5, 0);

        splatCsrSK<<<SG, B, 0, sS>>>();
        blur2SK<<<SG, B, 0, sS>>>(0, 1, 0);
        blurSK <<<SG, B, 0, sS>>>(2, 1);

        cudaEventRecord(eJoin, sS);
        cudaStreamWaitEvent(s0, eJoin, 0);

        sliceSoftmaxK<<<gridFor(NPIX,B), B, 0, s0>>>(
            unary, out, (it==4) ? 1 : 0,
            WB*ALPHA_B, WSPA*ALPHA_S);
    }
}